// round 1
// baseline (speedup 1.0000x reference)
#include <cuda_runtime.h>
#include <math.h>

// ---------------- problem constants ----------------
#define CB   4
#define CS   512
#define CD   2048
#define CNH  8
#define CDEG 4
#define CHD  256
#define CAH  16
#define CAHD 128
#define CDQ  512              // D/4
#define CNC  (CNH*CDEG*CHD)   // 8192

// ---------------- scratch (device globals; no allocation allowed) ----------
__device__ float g_xn   [CB*CS*CD];
__device__ float g_xmean[CB*CD];
__device__ float g_hs   [CB*CDQ];
__device__ float g_coef [CB*CNC];
__device__ float g_cheby[CB*CS*CD];
__device__ float g_kv   [CB*CS*CD];
__device__ float g_q    [CB*CS*CD];
__device__ float g_k    [CB*CS*CD];
__device__ float g_v    [CB*CS*CD];
__device__ float g_sc   [(size_t)CB*CAH*CS*CS];   // 64 MB attention scores/probs
__device__ float g_attn [CB*CS*CD];
__device__ float g_slr  [CB*CS*CD];
__device__ float g_hcat [CB*CS*2*CD];
__device__ float g_gv   [CB*CS*2*CD];
__device__ float g_fused[CB*CS*CD];

// ---------------- reductions (blockDim == 256 assumed) ----------------
__device__ __forceinline__ float warpSum(float v) {
    #pragma unroll
    for (int o = 16; o > 0; o >>= 1) v += __shfl_xor_sync(0xffffffffu, v, o);
    return v;
}
__device__ __forceinline__ float warpMax(float v) {
    #pragma unroll
    for (int o = 16; o > 0; o >>= 1) v = fmaxf(v, __shfl_xor_sync(0xffffffffu, v, o));
    return v;
}
__device__ __forceinline__ float blockSum(float v) {
    __shared__ float sh[8];
    v = warpSum(v);
    __syncthreads();
    if ((threadIdx.x & 31) == 0) sh[threadIdx.x >> 5] = v;
    __syncthreads();
    float r = sh[0];
    #pragma unroll
    for (int i = 1; i < 8; i++) r += sh[i];
    return r;
}
__device__ __forceinline__ float blockMax(float v) {
    __shared__ float shm[8];
    v = warpMax(v);
    __syncthreads();
    if ((threadIdx.x & 31) == 0) shm[threadIdx.x >> 5] = v;
    __syncthreads();
    float r = shm[0];
    #pragma unroll
    for (int i = 1; i < 8; i++) r = fmaxf(r, shm[i]);
    return r;
}

// ---------------- rmsnorm: one block (256 thr) per row of n elems ---------
__global__ void rmsnorm_kernel(const float* __restrict__ in,
                               const float* __restrict__ w,
                               float* __restrict__ out,
                               int n, long long ild, long long old_) {
    long long row = blockIdx.x;
    const float* ip = in + row * ild;
    float*       op = out + row * old_;
    float ss = 0.f;
    for (int i = threadIdx.x; i < n; i += 256) { float u = ip[i]; ss = fmaf(u, u, ss); }
    ss = blockSum(ss);
    float rs = rsqrtf(ss / (float)n + 1e-6f);
    for (int i = threadIdx.x; i < n; i += 256) op[i] = ip[i] * rs * w[i];
}

// ---------------- x_mean = mean over S of xn; one thread per (b,d) --------
__global__ void colmean_kernel(const float* __restrict__ xn, float* __restrict__ xm) {
    int idx = blockIdx.x * blockDim.x + threadIdx.x;      // b*CD + d
    int b = idx / CD, d = idx % CD;
    float s = 0.f;
    for (int t = 0; t < CS; t++) s += xn[((long long)b * CS + t) * CD + d];
    xm[idx] = s * (1.f / CS);
}

// ---------------- h = silu(x_mean @ wc1 + bc1); one warp per output -------
__global__ void mlp1_kernel(const float* __restrict__ xm, const float* __restrict__ wc1,
                            const float* __restrict__ bc1, float* __restrict__ h) {
    int gw   = (blockIdx.x * blockDim.x + threadIdx.x) >> 5;
    int lane = threadIdx.x & 31;
    int b = gw / CDQ, c = gw % CDQ;
    float s = 0.f;
    for (int k = lane; k < CD; k += 32) s = fmaf(xm[b * CD + k], wc1[(long long)k * CDQ + c], s);
    s = warpSum(s);
    if (lane == 0) {
        s += bc1[c];
        h[b * CDQ + c] = s / (1.f + expf(-s));
    }
}

// ------- coeffs = (h @ wc2 + bc2) * spectral_scale; one warp per output ----
__global__ void coeff_kernel(const float* __restrict__ h, const float* __restrict__ wc2,
                             const float* __restrict__ bc2, float* __restrict__ coef) {
    int gw   = (blockIdx.x * blockDim.x + threadIdx.x) >> 5;
    int lane = threadIdx.x & 31;
    int b = gw / CNC, c = gw % CNC;
    float s = 0.f;
    for (int k = lane; k < CDQ; k += 32) s = fmaf(h[b * CDQ + k], wc2[(long long)k * CNC + c], s);
    s = warpSum(s);
    if (lane == 0) {
        s += bc2[c];
        int kdeg = (c / CHD) % CDEG;
        coef[(long long)b * CNC + c] = s * (0.1f / (float)(kdeg + 1));
    }
}

// ------- cheby: per (b,s) row; 8 warps = 8 heads; writes cheby + kv --------
__global__ void cheby_kernel(const float* __restrict__ xn, const float* __restrict__ coef,
                             float* __restrict__ cheby, float* __restrict__ kv) {
    long long bs = blockIdx.x;
    int b = (int)(bs / CS);
    int w = threadIdx.x >> 5, lane = threadIdx.x & 31;   // head = w
    const float* u = xn + bs * CD + w * CHD;
    float s = 0.f;
    #pragma unroll
    for (int i = lane; i < CHD; i += 32) s += u[i];
    s = warpSum(s);
    float z = tanhf(s * (1.f / CHD));
    float T0 = 1.f, T1 = z, T2 = 2.f * z * z - 1.f, T3 = 2.f * z * T2 - T1;
    const float* cp = coef + (((long long)b * CNH + w) * CDEG) * CHD;
    float* co = cheby + bs * CD + w * CHD;
    float* ko = kv    + bs * CD + w * CHD;
    #pragma unroll
    for (int i = lane; i < CHD; i += 32) {
        float o = T0 * cp[i] + T1 * cp[CHD + i] + T2 * cp[2 * CHD + i] + T3 * cp[3 * CHD + i];
        co[i] = o;
        ko[i] = u[i] + o;
    }
}

// ---------------- tiled SGEMM: 128x128x8, 256 thr, 8x8/thread --------------
// C = alpha * A@B (+Add). TB=true: C[i,j] = sum_k A[i,k]*B[j,k].
// Batched: z -> (zo=z/bdiv, zi=z%bdiv), per-operand offsets.
template <bool TB>
__global__ void __launch_bounds__(256, 2)
sgemm_kernel(const float* __restrict__ A, const float* __restrict__ B,
             float* __restrict__ C, const float* __restrict__ Add,
             int K, int lda, int ldb, int ldc,
             int bdiv, long long sAo, long long sAi, long long sBo, long long sBi,
             long long sCo, long long sCi, float alpha) {
    int z  = blockIdx.z;
    int zo = z / bdiv, zi = z % bdiv;
    A += zo * sAo + zi * sAi;
    B += zo * sBo + zi * sBi;
    long long coff = zo * sCo + zi * sCi;

    __shared__ float As[8][128];
    __shared__ float Bs[8][128];

    const int tid  = threadIdx.x;
    const int row0 = blockIdx.y * 128, col0 = blockIdx.x * 128;
    const int tx = tid & 15, ty = tid >> 4;

    const int am = tid >> 1;          // 0..127
    const int ak = (tid & 1) << 2;    // 0 or 4
    const int bk = tid >> 5;          // 0..7
    const int bn = (tid & 31) << 2;   // 0..124

    float acc[8][8];
    #pragma unroll
    for (int i = 0; i < 8; i++)
        #pragma unroll
        for (int j = 0; j < 8; j++) acc[i][j] = 0.f;

    const float* Aptr = A + (long long)(row0 + am) * lda + ak;
    const float* Bptr = TB ? (B + (long long)(col0 + am) * ldb + ak)
                           : (B + (long long)bk * ldb + col0 + bn);

    for (int k0 = 0; k0 < K; k0 += 8) {
        float4 av = *(const float4*)(Aptr + k0);
        float4 bv = TB ? *(const float4*)(Bptr + k0)
                       : *(const float4*)(Bptr + (long long)k0 * ldb);
        __syncthreads();
        As[ak + 0][am] = av.x; As[ak + 1][am] = av.y;
        As[ak + 2][am] = av.z; As[ak + 3][am] = av.w;
        if (TB) {
            Bs[ak + 0][am] = bv.x; Bs[ak + 1][am] = bv.y;
            Bs[ak + 2][am] = bv.z; Bs[ak + 3][am] = bv.w;
        } else {
            *(float4*)&Bs[bk][bn] = bv;
        }
        __syncthreads();
        #pragma unroll
        for (int kk = 0; kk < 8; kk++) {
            float a[8], b[8];
            *(float4*)(a)     = *(const float4*)(&As[kk][ty * 8]);
            *(float4*)(a + 4) = *(const float4*)(&As[kk][ty * 8 + 4]);
            *(float4*)(b)     = *(const float4*)(&Bs[kk][tx * 8]);
            *(float4*)(b + 4) = *(const float4*)(&Bs[kk][tx * 8 + 4]);
            #pragma unroll
            for (int i = 0; i < 8; i++)
                #pragma unroll
                for (int j = 0; j < 8; j++)
                    acc[i][j] = fmaf(a[i], b[j], acc[i][j]);
        }
    }

    float* Cp = C + coff;
    const float* Ap2 = Add ? (Add + coff) : (const float*)0;
    #pragma unroll
    for (int i = 0; i < 8; i++) {
        long long r = (long long)(row0 + ty * 8 + i) * ldc + col0 + tx * 8;
        #pragma unroll
        for (int jq = 0; jq < 8; jq += 4) {
            float4 v;
            v.x = acc[i][jq + 0] * alpha;
            v.y = acc[i][jq + 1] * alpha;
            v.z = acc[i][jq + 2] * alpha;
            v.w = acc[i][jq + 3] * alpha;
            if (Ap2) {
                float4 ad = *(const float4*)(Ap2 + r + jq);
                v.x += ad.x; v.y += ad.y; v.z += ad.z; v.w += ad.w;
            }
            *(float4*)(Cp + r + jq) = v;
        }
    }
}

// ---------------- causal softmax over 512-wide rows ------------------------
__global__ void softmax_kernel(float* __restrict__ sc) {
    long long row = blockIdx.x;                 // (b,h,i) flattened
    int i = (int)(row % CS);
    float* sp = sc + row * CS;
    float e[2];
    float m = -1e30f;
    #pragma unroll
    for (int t = 0; t < 2; t++) { int j = threadIdx.x + t * 256; if (j <= i) m = fmaxf(m, sp[j]); }
    m = blockMax(m);
    float s = 0.f;
    #pragma unroll
    for (int t = 0; t < 2; t++) {
        int j = threadIdx.x + t * 256;
        float ev = (j <= i) ? expf(sp[j] - m) : 0.f;
        e[t] = ev; s += ev;
    }
    s = blockSum(s);
    float inv = 1.f / s;
    #pragma unroll
    for (int t = 0; t < 2; t++) { int j = threadIdx.x + t * 256; sp[j] = e[t] * inv; }
}

// -------- fused = rmsnorm(silu(gate)*value, w_np); one block per row -------
__global__ void fuse_kernel(const float* __restrict__ gv, const float* __restrict__ wnp,
                            float* __restrict__ fused) {
    long long row = blockIdx.x;
    const float* gp = gv + row * (2 * CD);
    float t[8];
    float ss = 0.f;
    #pragma unroll
    for (int ii = 0; ii < 8; ii++) {
        int i = threadIdx.x + ii * 256;
        float g = gp[i], v = gp[CD + i];
        float u = g / (1.f + expf(-g)) * v;
        t[ii] = u;
        ss = fmaf(u, u, ss);
    }
    ss = blockSum(ss);
    float rs = rsqrtf(ss * (1.f / CD) + 1e-6f);
    #pragma unroll
    for (int ii = 0; ii < 8; ii++) {
        int i = threadIdx.x + ii * 256;
        fused[row * CD + i] = t[ii] * rs * wnp[i];
    }
}

// ---------------- host launcher ----------------
static void run_sgemm(bool tb, const float* A, const float* B, float* C, const float* Add,
                      int M, int N, int K, int lda, int ldb, int ldc,
                      int bz, int bdiv,
                      long long sAo, long long sAi, long long sBo, long long sBi,
                      long long sCo, long long sCi, float alpha) {
    dim3 grid(N / 128, M / 128, bz), block(256);
    if (tb)
        sgemm_kernel<true><<<grid, block>>>(A, B, C, Add, K, lda, ldb, ldc,
                                            bdiv, sAo, sAi, sBo, sBi, sCo, sCi, alpha);
    else
        sgemm_kernel<false><<<grid, block>>>(A, B, C, Add, K, lda, ldb, ldc,
                                             bdiv, sAo, sAi, sBo, sBi, sCo, sCi, alpha);
}

extern "C" void kernel_launch(void* const* d_in, const int* in_sizes, int n_in,
                              void* d_out, int out_size) {
    const float* x     = (const float*)d_in[0];
    const float* w_in  = (const float*)d_in[1];
    // d_in[2..5] (wg1,bg1,wg2,bg2) are dead: gate only feeds unused coeff update
    const float* wc1   = (const float*)d_in[6];
    const float* bc1   = (const float*)d_in[7];
    const float* wc2   = (const float*)d_in[8];
    const float* bc2   = (const float*)d_in[9];
    const float* wq    = (const float*)d_in[10];
    const float* wk    = (const float*)d_in[11];
    const float* wv    = (const float*)d_in[12];
    const float* wo    = (const float*)d_in[13];
    const float* w_nc  = (const float*)d_in[14];
    const float* w_ns  = (const float*)d_in[15];
    const float* w_fgv = (const float*)d_in[16];
    const float* w_np  = (const float*)d_in[17];
    const float* w_out = (const float*)d_in[18];
    float* out = (float*)d_out;

    float *xn, *xm, *hs, *coef, *cheb, *kv, *q, *k, *v, *sc, *attn, *slr, *hcat, *gv, *fused;
    cudaGetSymbolAddress((void**)&xn,    g_xn);
    cudaGetSymbolAddress((void**)&xm,    g_xmean);
    cudaGetSymbolAddress((void**)&hs,    g_hs);
    cudaGetSymbolAddress((void**)&coef,  g_coef);
    cudaGetSymbolAddress((void**)&cheb,  g_cheby);
    cudaGetSymbolAddress((void**)&kv,    g_kv);
    cudaGetSymbolAddress((void**)&q,     g_q);
    cudaGetSymbolAddress((void**)&k,     g_k);
    cudaGetSymbolAddress((void**)&v,     g_v);
    cudaGetSymbolAddress((void**)&sc,    g_sc);
    cudaGetSymbolAddress((void**)&attn,  g_attn);
    cudaGetSymbolAddress((void**)&slr,   g_slr);
    cudaGetSymbolAddress((void**)&hcat,  g_hcat);
    cudaGetSymbolAddress((void**)&gv,    g_gv);
    cudaGetSymbolAddress((void**)&fused, g_fused);

    const int MT = CB * CS;  // 2048 tokens

    // 1) xn = rmsnorm(x, w_in)
    rmsnorm_kernel<<<MT, 256>>>(x, w_in, xn, CD, CD, CD);
    // 2) x_mean over S
    colmean_kernel<<<(CB * CD) / 256, 256>>>(xn, xm);
    // 3) h = silu(x_mean @ wc1 + bc1)    (4 x 512)
    mlp1_kernel<<<(CB * CDQ) / 8, 256>>>(xm, wc1, bc1, hs);
    // 4) coeffs = (h @ wc2 + bc2) * spectral_scale   (4 x 8192)
    coeff_kernel<<<(CB * CNC) / 8, 256>>>(hs, wc2, bc2, coef);
    // 5) cheby_out + kv_src
    cheby_kernel<<<MT, 256>>>(xn, coef, cheb, kv);

    // 6) q = xn @ wq ; k = kv @ wk ; v = kv @ wv   (2048x2048x2048 each)
    run_sgemm(false, xn, wq, q, 0, MT, CD, CD, CD, CD, CD, 1, 1, 0, 0, 0, 0, 0, 0, 1.f);
    run_sgemm(false, kv, wk, k, 0, MT, CD, CD, CD, CD, CD, 1, 1, 0, 0, 0, 0, 0, 0, 1.f);
    run_sgemm(false, kv, wv, v, 0, MT, CD, CD, CD, CD, CD, 1, 1, 0, 0, 0, 0, 0, 0, 1.f);

    // 7) scores = q @ k^T / sqrt(128), per (b,head); z = b*16 + h
    run_sgemm(true, q, k, sc, 0, CS, CS, CAHD, CD, CD, CS,
              CB * CAH, CAH,
              (long long)CS * CD, CAHD,
              (long long)CS * CD, CAHD,
              (long long)CAH * CS * CS, (long long)CS * CS,
              0.08838834764831845f);
    // 8) causal softmax
    softmax_kernel<<<CB * CAH * CS, 256>>>(sc);
    // 9) attn = P @ V   (per head, N=128)
    run_sgemm(false, sc, v, attn, 0, CS, CAHD, CS, CS, CD, CD,
              CB * CAH, CAH,
              (long long)CAH * CS * CS, (long long)CS * CS,
              (long long)CS * CD, CAHD,
              (long long)CS * CD, CAHD, 1.f);
    // 10) slr = attn @ wo
    run_sgemm(false, attn, wo, slr, 0, MT, CD, CD, CD, CD, CD, 1, 1, 0, 0, 0, 0, 0, 0, 1.f);

    // 11) hcat = [rmsnorm(cheby, w_nc), rmsnorm(slr, w_ns)]
    rmsnorm_kernel<<<MT, 256>>>(cheb, w_nc, hcat, CD, CD, 2 * CD);
    rmsnorm_kernel<<<MT, 256>>>(slr, w_ns, hcat + CD, CD, CD, 2 * CD);
    // 12) gv = hcat @ w_fgv   (2048 x 4096 x 4096)
    run_sgemm(false, hcat, w_fgv, gv, 0, MT, 2 * CD, 2 * CD, 2 * CD, 2 * CD, 2 * CD,
              1, 1, 0, 0, 0, 0, 0, 0, 1.f);
    // 13) fused = rmsnorm(silu(gate)*value, w_np)
    fuse_kernel<<<MT, 256>>>(gv, w_np, fused);
    // 14) out = x + fused @ w_out
    run_sgemm(false, fused, w_out, out, x, MT, CD, CD, CD, CD, CD,
              1, 1, 0, 0, 0, 0, 0, 0, 1.f);
}

// round 3
// speedup vs baseline: 1.6003x; 1.6003x over previous
#include <cuda_runtime.h>
#include <cuda_bf16.h>
#include <cstdint>
#include <math.h>

// ---------------- problem constants ----------------
#define CB   4
#define CS   512
#define CD   2048
#define CNH  8
#define CDEG 4
#define CHD  256
#define CAH  16
#define CAHD 128
#define CDQ  512              // D/4
#define CNC  (CNH*CDEG*CHD)   // 8192
#define MT   (CB*CS)          // 2048 tokens

// ---------------- fp32 scratch ----------------
__device__ float g_xn   [MT*CD];
__device__ float g_xmean[CB*CD];
__device__ float g_hs   [CB*CDQ];
__device__ float g_coef [CB*CNC];
__device__ float g_cheby[MT*CD];
__device__ float g_q    [MT*CD];
__device__ float g_k    [MT*CD];
__device__ float g_v    [MT*CD];
__device__ float g_sc   [(size_t)CB*CAH*CS*CS];
__device__ float g_attn [MT*CD];
__device__ float g_slr  [MT*CD];
__device__ float g_gv   [MT*2*CD];

// ---------------- bf16 split scratch (3x K) ----------------
__device__ __align__(16) __nv_bfloat16 g3_xn  [MT*3*CD];
__device__ __align__(16) __nv_bfloat16 g3_kv  [MT*3*CD];
__device__ __align__(16) __nv_bfloat16 g3_attn[MT*3*CD];
__device__ __align__(16) __nv_bfloat16 g3_fus [MT*3*CD];
__device__ __align__(16) __nv_bfloat16 g3_hcat[(size_t)MT*3*2*CD];
__device__ __align__(16) __nv_bfloat16 g3_q   [MT*3*CD];
__device__ __align__(16) __nv_bfloat16 g3_k   [MT*3*CD];
__device__ __align__(16) __nv_bfloat16 g3_wq  [(size_t)CD*3*CD];
__device__ __align__(16) __nv_bfloat16 g3_wk  [(size_t)CD*3*CD];
__device__ __align__(16) __nv_bfloat16 g3_wv  [(size_t)CD*3*CD];
__device__ __align__(16) __nv_bfloat16 g3_wo  [(size_t)CD*3*CD];
__device__ __align__(16) __nv_bfloat16 g3_wout[(size_t)CD*3*CD];
__device__ __align__(16) __nv_bfloat16 g3_wfgv[(size_t)(2*CD)*3*(2*CD)];

// ---------------- helpers ----------------
__device__ __forceinline__ uint32_t smem_u32(const void* p) {
    uint32_t a;
    asm("{ .reg .u64 t; cvta.to.shared.u64 t, %1; cvt.u32.u64 %0, t; }" : "=r"(a) : "l"(p));
    return a;
}
__device__ __forceinline__ void cp16(uint32_t dst, const void* src) {
    asm volatile("cp.async.cg.shared.global [%0], [%1], 16;" :: "r"(dst), "l"(src) : "memory");
}
__device__ __forceinline__ void cp_commit() { asm volatile("cp.async.commit_group;" ::: "memory"); }

__device__ __forceinline__ void ldm_x4(uint32_t addr, uint32_t& r0, uint32_t& r1,
                                       uint32_t& r2, uint32_t& r3) {
    asm volatile("ldmatrix.sync.aligned.m8n8.x4.shared.b16 {%0,%1,%2,%3}, [%4];"
                 : "=r"(r0), "=r"(r1), "=r"(r2), "=r"(r3) : "r"(addr));
}
__device__ __forceinline__ void mma16816(float* c, const uint32_t* a, const uint32_t* b) {
    asm volatile("mma.sync.aligned.m16n8k16.row.col.f32.bf16.bf16.f32 "
                 "{%0,%1,%2,%3}, {%4,%5,%6,%7}, {%8,%9}, {%0,%1,%2,%3};"
                 : "+f"(c[0]), "+f"(c[1]), "+f"(c[2]), "+f"(c[3])
                 : "r"(a[0]), "r"(a[1]), "r"(a[2]), "r"(a[3]), "r"(b[0]), "r"(b[1]));
}

// ---------------- bf16 hi/lo split ----------------
__device__ __forceinline__ void split2(float a, __nv_bfloat16& hi, __nv_bfloat16& lo) {
    hi = __float2bfloat16(a);
    lo = __float2bfloat16(a - __bfloat162float(hi));
}

// ---------------- reductions ----------------
__device__ __forceinline__ float warpSum(float v) {
    #pragma unroll
    for (int o = 16; o > 0; o >>= 1) v += __shfl_xor_sync(0xffffffffu, v, o);
    return v;
}
__device__ __forceinline__ float warpMax(float v) {
    #pragma unroll
    for (int o = 16; o > 0; o >>= 1) v = fmaxf(v, __shfl_xor_sync(0xffffffffu, v, o));
    return v;
}
__device__ __forceinline__ float blockSum(float v) {
    __shared__ float sh[8];
    v = warpSum(v);
    __syncthreads();
    if ((threadIdx.x & 31) == 0) sh[threadIdx.x >> 5] = v;
    __syncthreads();
    float r = sh[0];
    #pragma unroll
    for (int i = 1; i < 8; i++) r += sh[i];
    return r;
}
__device__ __forceinline__ float blockMax(float v) {
    __shared__ float shm[8];
    v = warpMax(v);
    __syncthreads();
    if ((threadIdx.x & 31) == 0) shm[threadIdx.x >> 5] = v;
    __syncthreads();
    float r = shm[0];
    #pragma unroll
    for (int i = 1; i < 8; i++) r = fmaxf(r, shm[i]);
    return r;
}

// =================== HMMA bf16 GEMM: 128x128 tile, BK=32, 8 warps =========
// A [M, lda] row-major bf16 (K contiguous); B [N, ldb] row-major bf16
// (K contiguous, i.e. transposed weight). C = alpha*A@B^T (+Add) fp32.
// Padded smem rows: 32 bf16 data + pad -> 80-byte stride (conflict-free ldmatrix).
#define ROWB 80
#define TILEB (128*ROWB)     // 10240 per matrix
#define STGB  (2*TILEB)      // 20480 per stage

__global__ void __launch_bounds__(256, 2)
mm_bf16_kernel(const __nv_bfloat16* __restrict__ A, const __nv_bfloat16* __restrict__ B,
               float* __restrict__ C, const float* __restrict__ Add,
               int lda, int ldb, int ldc, int K3, float alpha,
               int bdiv, long long sAo, long long sAi, long long sBo, long long sBi,
               long long sCo, long long sCi) {
    __shared__ __align__(128) char sm[2 * STGB];

    int z = blockIdx.z, zo = z / bdiv, zi = z - zo * bdiv;
    A += zo * sAo + zi * sAi;
    B += zo * sBo + zi * sBi;
    long long coff = zo * sCo + zi * sCi;

    const int tid  = threadIdx.x, lane = tid & 31, wid = tid >> 5;
    const int wm   = wid >> 2, wn = wid & 3;           // 2 x 4 warps
    const int row0 = blockIdx.y * 128, col0 = blockIdx.x * 128;

    const uint32_t sbase = smem_u32(sm);
    const int lrow = tid >> 1;               // 0..127
    const int lch  = (tid & 1) * 2;          // 0 or 2 (16B chunks)

    const __nv_bfloat16* Agb = A + (long long)(row0 + lrow) * lda + lch * 8;
    const __nv_bfloat16* Bgb = B + (long long)(col0 + lrow) * ldb + lch * 8;
    const uint32_t sAw = sbase + lrow * ROWB + lch * 16;
    const uint32_t sBw = sAw + TILEB;

    auto load_stage = [&](int kc, int st) {
        uint32_t o = st * STGB;
        const __nv_bfloat16* Ag = Agb + kc * 32;
        const __nv_bfloat16* Bg = Bgb + kc * 32;
        cp16(sAw + o,      Ag);
        cp16(sAw + o + 16, Ag + 8);
        cp16(sBw + o,      Bg);
        cp16(sBw + o + 16, Bg + 8);
        cp_commit();
    };

    float acc[4][4][4];
    #pragma unroll
    for (int i = 0; i < 4; i++)
        #pragma unroll
        for (int j = 0; j < 4; j++)
            #pragma unroll
            for (int e = 0; e < 4; e++) acc[i][j][e] = 0.f;

    const int NK = K3 / 32;
    load_stage(0, 0);

    // ldmatrix lane addressing
    const int lr15 = lane & 15, lhi = lane >> 4;
    const uint32_t aoff = (uint32_t)((wm * 64 + lr15) * ROWB + lhi * 16);
    const uint32_t boff = (uint32_t)((wn * 32 + lr15) * ROWB + lhi * 16) + TILEB;

    for (int kc = 0; kc < NK; kc++) {
        int st = kc & 1;
        if (kc + 1 < NK) {
            load_stage(kc + 1, st ^ 1);
            asm volatile("cp.async.wait_group 1;" ::: "memory");
        } else {
            asm volatile("cp.async.wait_group 0;" ::: "memory");
        }
        __syncthreads();

        uint32_t sA = sbase + st * STGB + aoff;
        uint32_t sB = sbase + st * STGB + boff;
        #pragma unroll
        for (int ks = 0; ks < 2; ks++) {
            uint32_t a[4][4];
            #pragma unroll
            for (int mt = 0; mt < 4; mt++)
                ldm_x4(sA + mt * (16 * ROWB) + ks * 32, a[mt][0], a[mt][1], a[mt][2], a[mt][3]);
            uint32_t b[4][2];
            #pragma unroll
            for (int bt = 0; bt < 2; bt++) {
                uint32_t r0, r1, r2, r3;
                ldm_x4(sB + bt * (16 * ROWB) + ks * 32, r0, r1, r2, r3);
                b[bt * 2 + 0][0] = r0; b[bt * 2 + 0][1] = r2;
                b[bt * 2 + 1][0] = r1; b[bt * 2 + 1][1] = r3;
            }
            #pragma unroll
            for (int mt = 0; mt < 4; mt++)
                #pragma unroll
                for (int nt = 0; nt < 4; nt++)
                    mma16816(acc[mt][nt], a[mt], b[nt]);
        }
        __syncthreads();
    }

    // ---- epilogue ----
    const int erow = row0 + wm * 64 + (lane >> 2);
    const int ecol = col0 + wn * 32 + (lane & 3) * 2;
    #pragma unroll
    for (int mt = 0; mt < 4; mt++) {
        #pragma unroll
        for (int half = 0; half < 2; half++) {
            long long r = (long long)(erow + mt * 16 + half * 8) * ldc + ecol + coff;
            #pragma unroll
            for (int nt = 0; nt < 4; nt++) {
                float2 v;
                v.x = acc[mt][nt][half * 2 + 0] * alpha;
                v.y = acc[mt][nt][half * 2 + 1] * alpha;
                if (Add) {
                    float2 ad = *(const float2*)(Add + r + nt * 8);
                    v.x += ad.x; v.y += ad.y;
                }
                *(float2*)(C + r + nt * 8) = v;
            }
        }
    }
}

// =================== elementwise / prep kernels ===================

__global__ void rmsnorm_split_kernel(const float* __restrict__ in, const float* __restrict__ w,
                                     float* __restrict__ outf, __nv_bfloat16* __restrict__ out3,
                                     int Ktot, int colofs) {
    long long row = blockIdx.x;
    const float* ip = in + row * CD;
    float vals[8], ss = 0.f;
    #pragma unroll
    for (int ii = 0; ii < 8; ii++) {
        float u = ip[threadIdx.x + ii * 256];
        vals[ii] = u; ss = fmaf(u, u, ss);
    }
    ss = blockSum(ss);
    float rs = rsqrtf(ss * (1.f / CD) + 1e-6f);
    long long b3 = row * 3LL * Ktot + colofs;
    #pragma unroll
    for (int ii = 0; ii < 8; ii++) {
        int i = threadIdx.x + ii * 256;
        float u = vals[ii] * rs * w[i];
        if (outf) outf[row * CD + i] = u;
        __nv_bfloat16 hi, lo; split2(u, hi, lo);
        out3[b3 + i] = hi;
        out3[b3 + Ktot + i] = hi;
        out3[b3 + 2 * Ktot + i] = lo;
    }
}

__global__ void colmean_kernel(const float* __restrict__ xn, float* __restrict__ xm) {
    int idx = blockIdx.x * blockDim.x + threadIdx.x;
    int b = idx / CD, d = idx % CD;
    float s = 0.f;
    for (int t = 0; t < CS; t++) s += xn[((long long)b * CS + t) * CD + d];
    xm[idx] = s * (1.f / CS);
}

__global__ void mlp2_kernel(const float* __restrict__ xm, const float* __restrict__ wc1,
                            const float* __restrict__ bc1, float* __restrict__ h) {
    int b = blockIdx.y, c = blockIdx.x * 256 + threadIdx.x;
    float s = 0.f;
    for (int k = 0; k < CD; k++) s = fmaf(xm[b * CD + k], wc1[(long long)k * CDQ + c], s);
    s += bc1[c];
    h[b * CDQ + c] = s / (1.f + expf(-s));
}

__global__ void coeff2_kernel(const float* __restrict__ h, const float* __restrict__ wc2,
                              const float* __restrict__ bc2, float* __restrict__ coef) {
    int b = blockIdx.y, c = blockIdx.x * 256 + threadIdx.x;
    float s = 0.f;
    for (int k = 0; k < CDQ; k++) s = fmaf(h[b * CDQ + k], wc2[(long long)k * CNC + c], s);
    s += bc2[c];
    int kdeg = (c / CHD) % CDEG;
    coef[(long long)b * CNC + c] = s * (0.1f / (float)(kdeg + 1));
}

__global__ void cheby2_kernel(const float* __restrict__ xn, const float* __restrict__ coef,
                              float* __restrict__ cheby, __nv_bfloat16* __restrict__ kv3) {
    long long bs = blockIdx.x;
    int b = (int)(bs / CS);
    int w = threadIdx.x >> 5, lane = threadIdx.x & 31;
    const float* u = xn + bs * CD + w * CHD;
    float s = 0.f;
    #pragma unroll
    for (int i = lane; i < CHD; i += 32) s += u[i];
    s = warpSum(s);
    float z = tanhf(s * (1.f / CHD));
    float T1 = z, T2 = 2.f * z * z - 1.f, T3 = 2.f * z * T2 - T1;
    const float* cp = coef + (((long long)b * CNH + w) * CDEG) * CHD;
    float* co = cheby + bs * CD + w * CHD;
    long long b3 = bs * (3LL * CD) + w * CHD;
    #pragma unroll
    for (int i = lane; i < CHD; i += 32) {
        float o = cp[i] + T1 * cp[CHD + i] + T2 * cp[2 * CHD + i] + T3 * cp[3 * CHD + i];
        co[i] = o;
        float val = u[i] + o;
        __nv_bfloat16 hi, lo; split2(val, hi, lo);
        kv3[b3 + i] = hi;
        kv3[b3 + CD + i] = hi;
        kv3[b3 + 2 * CD + i] = lo;
    }
}

// transpose + B-side split (hi,lo,hi): W[K,N] fp32 -> Y[N,3K] bf16
__global__ void transpose_split_kernel(const float* __restrict__ W, __nv_bfloat16* __restrict__ Y,
                                       int K, int N) {
    __shared__ float t[32][33];
    int k0 = blockIdx.y * 32, n0 = blockIdx.x * 32;
    int tx = threadIdx.x, ty = threadIdx.y;
    #pragma unroll
    for (int i = 0; i < 4; i++) {
        int k = k0 + ty + i * 8;
        t[ty + i * 8][tx] = W[(long long)k * N + n0 + tx];
    }
    __syncthreads();
    #pragma unroll
    for (int i = 0; i < 4; i++) {
        int n = n0 + ty + i * 8;
        int k = k0 + tx;
        float a = t[tx][ty + i * 8];
        __nv_bfloat16 hi, lo; split2(a, hi, lo);
        long long base = (long long)n * 3 * K;
        Y[base + k] = hi;
        Y[base + K + k] = lo;
        Y[base + 2 * K + k] = hi;
    }
}

__global__ void split_plain_kernel(const float* __restrict__ X, __nv_bfloat16* __restrict__ Y) {
    int m = blockIdx.y, c = blockIdx.x * 256 + threadIdx.x;
    float a = X[(long long)m * CD + c];
    __nv_bfloat16 hi, lo; split2(a, hi, lo);
    long long base = (long long)m * 3 * CD;
    Y[base + c] = hi;
    Y[base + CD + c] = hi;
    Y[base + 2 * CD + c] = lo;
}

// per-head split: X[M,2048] -> Y[M, 16*(3*128)]; bside: (hi,lo,hi) else (hi,hi,lo)
__global__ void split_heads_kernel(const float* __restrict__ X, __nv_bfloat16* __restrict__ Y,
                                   int bside) {
    int m = blockIdx.y, c = blockIdx.x * 256 + threadIdx.x;
    int h = c >> 7, d = c & 127;
    float a = X[(long long)m * CD + c];
    __nv_bfloat16 hi, lo; split2(a, hi, lo);
    long long base = (long long)m * (3 * CD) + (long long)h * 384;
    Y[base + d] = hi;
    Y[base + 128 + d] = bside ? lo : hi;
    Y[base + 256 + d] = bside ? hi : lo;
}

__global__ void fuse_split_kernel(const float* __restrict__ gv, const float* __restrict__ wnp,
                                  __nv_bfloat16* __restrict__ out3) {
    long long row = blockIdx.x;
    const float* gp = gv + row * (2 * CD);
    float t[8], ss = 0.f;
    #pragma unroll
    for (int ii = 0; ii < 8; ii++) {
        int i = threadIdx.x + ii * 256;
        float g = gp[i], v = gp[CD + i];
        float u = g / (1.f + expf(-g)) * v;
        t[ii] = u; ss = fmaf(u, u, ss);
    }
    ss = blockSum(ss);
    float rs = rsqrtf(ss * (1.f / CD) + 1e-6f);
    long long b3 = row * (3LL * CD);
    #pragma unroll
    for (int ii = 0; ii < 8; ii++) {
        int i = threadIdx.x + ii * 256;
        float u = t[ii] * rs * wnp[i];
        __nv_bfloat16 hi, lo; split2(u, hi, lo);
        out3[b3 + i] = hi;
        out3[b3 + CD + i] = hi;
        out3[b3 + 2 * CD + i] = lo;
    }
}

// ---------------- fp32 SGEMM (kept for PV only) ----------------
__global__ void __launch_bounds__(256, 2)
sgemm_kernel(const float* __restrict__ A, const float* __restrict__ B,
             float* __restrict__ C, int K, int lda, int ldb, int ldc,
             int bdiv, long long sAo, long long sAi, long long sBo, long long sBi,
             long long sCo, long long sCi) {
    int z = blockIdx.z, zo = z / bdiv, zi = z % bdiv;
    A += zo * sAo + zi * sAi;
    B += zo * sBo + zi * sBi;
    long long coff = zo * sCo + zi * sCi;

    __shared__ float As[8][128];
    __shared__ float Bs[8][128];
    const int tid = threadIdx.x;
    const int row0 = blockIdx.y * 128, col0 = blockIdx.x * 128;
    const int tx = tid & 15, ty = tid >> 4;
    const int am = tid >> 1, ak = (tid & 1) << 2;
    const int bk = tid >> 5, bn = (tid & 31) << 2;

    float acc[8][8];
    #pragma unroll
    for (int i = 0; i < 8; i++)
        #pragma unroll
        for (int j = 0; j < 8; j++) acc[i][j] = 0.f;

    const float* Aptr = A + (long long)(row0 + am) * lda + ak;
    const float* Bptr = B + (long long)bk * ldb + col0 + bn;

    for (int k0 = 0; k0 < K; k0 += 8) {
        float4 av = *(const float4*)(Aptr + k0);
        float4 bv = *(const float4*)(Bptr + (long long)k0 * ldb);
        __syncthreads();
        As[ak + 0][am] = av.x; As[ak + 1][am] = av.y;
        As[ak + 2][am] = av.z; As[ak + 3][am] = av.w;
        *(float4*)&Bs[bk][bn] = bv;
        __syncthreads();
        #pragma unroll
        for (int kk = 0; kk < 8; kk++) {
            float a[8], b[8];
            *(float4*)(a)     = *(const float4*)(&As[kk][ty * 8]);
            *(float4*)(a + 4) = *(const float4*)(&As[kk][ty * 8 + 4]);
            *(float4*)(b)     = *(const float4*)(&Bs[kk][tx * 8]);
            *(float4*)(b + 4) = *(const float4*)(&Bs[kk][tx * 8 + 4]);
            #pragma unroll
            for (int i = 0; i < 8; i++)
                #pragma unroll
                for (int j = 0; j < 8; j++)
                    acc[i][j] = fmaf(a[i], b[j], acc[i][j]);
        }
    }
    float* Cp = C + coff;
    #pragma unroll
    for (int i = 0; i < 8; i++) {
        long long r = (long long)(row0 + ty * 8 + i) * ldc + col0 + tx * 8;
        #pragma unroll
        for (int jq = 0; jq < 8; jq += 4) {
            float4 v;
            v.x = acc[i][jq + 0]; v.y = acc[i][jq + 1];
            v.z = acc[i][jq + 2]; v.w = acc[i][jq + 3];
            *(float4*)(Cp + r + jq) = v;
        }
    }
}

// ---------------- causal softmax over 512-wide rows ------------------------
__global__ void softmax_kernel(float* __restrict__ sc) {
    long long row = blockIdx.x;
    int i = (int)(row % CS);
    float* sp = sc + row * CS;
    float e[2];
    float m = -1e30f;
    #pragma unroll
    for (int t = 0; t < 2; t++) { int j = threadIdx.x + t * 256; if (j <= i) m = fmaxf(m, sp[j]); }
    m = blockMax(m);
    float s = 0.f;
    #pragma unroll
    for (int t = 0; t < 2; t++) {
        int j = threadIdx.x + t * 256;
        float ev = (j <= i) ? expf(sp[j] - m) : 0.f;
        e[t] = ev; s += ev;
    }
    s = blockSum(s);
    float inv = 1.f / s;
    #pragma unroll
    for (int t = 0; t < 2; t++) { int j = threadIdx.x + t * 256; sp[j] = e[t] * inv; }
}

// ---------------- host ----------------
static void mm(const __nv_bfloat16* A, const __nv_bfloat16* B, float* C, const float* Add,
               int M, int N, int K3, int lda, int ldb, int ldc, float alpha,
               int bz, int bdiv, long long sAo, long long sAi, long long sBo, long long sBi,
               long long sCo, long long sCi) {
    dim3 grid(N / 128, M / 128, bz);
    mm_bf16_kernel<<<grid, 256>>>(A, B, C, Add, lda, ldb, ldc, K3, alpha,
                                  bdiv, sAo, sAi, sBo, sBi, sCo, sCi);
}

extern "C" void kernel_launch(void* const* d_in, const int* in_sizes, int n_in,
                              void* d_out, int out_size) {
    const float* x     = (const float*)d_in[0];
    const float* w_in  = (const float*)d_in[1];
    const float* wc1   = (const float*)d_in[6];
    const float* bc1   = (const float*)d_in[7];
    const float* wc2   = (const float*)d_in[8];
    const float* bc2   = (const float*)d_in[9];
    const float* wq    = (const float*)d_in[10];
    const float* wk    = (const float*)d_in[11];
    const float* wv    = (const float*)d_in[12];
    const float* wo    = (const float*)d_in[13];
    const float* w_nc  = (const float*)d_in[14];
    const float* w_ns  = (const float*)d_in[15];
    const float* w_fgv = (const float*)d_in[16];
    const float* w_np  = (const float*)d_in[17];
    const float* w_out = (const float*)d_in[18];
    float* out = (float*)d_out;

    float *xn, *xm, *hs, *coef, *cheb, *q, *k, *v, *sc, *attn, *slr, *gvb;
    cudaGetSymbolAddress((void**)&xn,   g_xn);
    cudaGetSymbolAddress((void**)&xm,   g_xmean);
    cudaGetSymbolAddress((void**)&hs,   g_hs);
    cudaGetSymbolAddress((void**)&coef, g_coef);
    cudaGetSymbolAddress((void**)&cheb, g_cheby);
    cudaGetSymbolAddress((void**)&q,    g_q);
    cudaGetSymbolAddress((void**)&k,    g_k);
    cudaGetSymbolAddress((void**)&v,    g_v);
    cudaGetSymbolAddress((void**)&sc,   g_sc);
    cudaGetSymbolAddress((void**)&attn, g_attn);
    cudaGetSymbolAddress((void**)&slr,  g_slr);
    cudaGetSymbolAddress((void**)&gvb,  g_gv);

    __nv_bfloat16 *xn3, *kv3, *attn3, *fus3, *hcat3, *q3, *k3;
    __nv_bfloat16 *wq3, *wk3, *wv3, *wo3, *wout3, *wfgv3;
    cudaGetSymbolAddress((void**)&xn3,   g3_xn);
    cudaGetSymbolAddress((void**)&kv3,   g3_kv);
    cudaGetSymbolAddress((void**)&attn3, g3_attn);
    cudaGetSymbolAddress((void**)&fus3,  g3_fus);
    cudaGetSymbolAddress((void**)&hcat3, g3_hcat);
    cudaGetSymbolAddress((void**)&q3,    g3_q);
    cudaGetSymbolAddress((void**)&k3,    g3_k);
    cudaGetSymbolAddress((void**)&wq3,   g3_wq);
    cudaGetSymbolAddress((void**)&wk3,   g3_wk);
    cudaGetSymbolAddress((void**)&wv3,   g3_wv);
    cudaGetSymbolAddress((void**)&wo3,   g3_wo);
    cudaGetSymbolAddress((void**)&wout3, g3_wout);
    cudaGetSymbolAddress((void**)&wfgv3, g3_wfgv);

    // weight transposes + B-side splits
    dim3 tgrid(CD / 32, CD / 32), tblk(32, 8);
    transpose_split_kernel<<<tgrid, tblk>>>(wq,    wq3,   CD, CD);
    transpose_split_kernel<<<tgrid, tblk>>>(wk,    wk3,   CD, CD);
    transpose_split_kernel<<<tgrid, tblk>>>(wv,    wv3,   CD, CD);
    transpose_split_kernel<<<tgrid, tblk>>>(wo,    wo3,   CD, CD);
    transpose_split_kernel<<<tgrid, tblk>>>(w_out, wout3, CD, CD);
    dim3 tgrid2((2 * CD) / 32, (2 * CD) / 32);
    transpose_split_kernel<<<tgrid2, tblk>>>(w_fgv, wfgv3, 2 * CD, 2 * CD);

    // activations prep
    rmsnorm_split_kernel<<<MT, 256>>>(x, w_in, xn, xn3, CD, 0);
    colmean_kernel<<<(CB * CD) / 256, 256>>>(xn, xm);
    mlp2_kernel<<<dim3(CDQ / 256, CB), 256>>>(xm, wc1, bc1, hs);
    coeff2_kernel<<<dim3(CNC / 256, CB), 256>>>(hs, wc2, bc2, coef);
    cheby2_kernel<<<MT, 256>>>(xn, coef, cheb, kv3);

    // q/k/v projections (HMMA, 3-term split)
    mm(xn3, wq3, q, 0, MT, CD, 3 * CD, 3 * CD, 3 * CD, CD, 1.f, 1, 1, 0, 0, 0, 0, 0, 0);
    mm(kv3, wk3, k, 0, MT, CD, 3 * CD, 3 * CD, 3 * CD, CD, 1.f, 1, 1, 0, 0, 0, 0, 0, 0);
    mm(kv3, wv3, v, 0, MT, CD, 3 * CD, 3 * CD, 3 * CD, CD, 1.f, 1, 1, 0, 0, 0, 0, 0, 0);

    // per-head re-splits for attention
    split_heads_kernel<<<dim3(CD / 256, MT), 256>>>(q, q3, 0);
    split_heads_kernel<<<dim3(CD / 256, MT), 256>>>(k, k3, 1);

    // scores = q @ k^T / sqrt(hd)  (batched over b,h)
    mm(q3, k3, sc, 0, CS, CS, 384, 3 * CD, 3 * CD, CS, 0.08838834764831845f,
       CB * CAH, CAH,
       (long long)CS * 3 * CD, 384,
       (long long)CS * 3 * CD, 384,
       (long long)CAH * CS * CS, (long long)CS * CS);

    softmax_kernel<<<CB * CAH * CS, 256>>>(sc);

    // attn = P @ V  (fp32 SGEMM, per head)
    {
        dim3 grid(CAHD / 128, CS / 128, CB * CAH);
        sgemm_kernel<<<grid, 256>>>(sc, v, attn, CS, CS, CD, CD,
                                    CAH,
                                    (long long)CAH * CS * CS, (long long)CS * CS,
                                    (long long)CS * CD, CAHD,
                                    (long long)CS * CD, CAHD);
    }

    // slr = attn @ wo
    split_plain_kernel<<<dim3(CD / 256, MT), 256>>>(attn, attn3);
    mm(attn3, wo3, slr, 0, MT, CD, 3 * CD, 3 * CD, 3 * CD, CD, 1.f, 1, 1, 0, 0, 0, 0, 0, 0);

    // hcat3 = split([rmsnorm(cheb), rmsnorm(slr)])
    rmsnorm_split_kernel<<<MT, 256>>>(cheb, w_nc, 0, hcat3, 2 * CD, 0);
    rmsnorm_split_kernel<<<MT, 256>>>(slr,  w_ns, 0, hcat3, 2 * CD, CD);

    // gv = hcat @ w_fgv
    mm(hcat3, wfgv3, gvb, 0, MT, 2 * CD, 3 * 2 * CD, 3 * 2 * CD, 3 * 2 * CD, 2 * CD, 1.f,
       1, 1, 0, 0, 0, 0, 0, 0);

    // fused, then out = x + fused @ w_out
    fuse_split_kernel<<<MT, 256>>>(gvb, w_np, fus3);
    mm(fus3, wout3, out, x, MT, CD, 3 * CD, 3 * CD, 3 * CD, CD, 1.f, 1, 1, 0, 0, 0, 0, 0, 0);
}

// round 4
// speedup vs baseline: 1.6804x; 1.0500x over previous
#include <cuda_runtime.h>
#include <cuda_bf16.h>
#include <cstdint>
#include <math.h>

// ---------------- problem constants ----------------
#define CB   4
#define CS   512
#define CD   2048
#define CNH  8
#define CDEG 4
#define CHD  256
#define CAH  16
#define CAHD 128
#define CDQ  512              // D/4
#define CNC  (CNH*CDEG*CHD)   // 8192
#define MT   (CB*CS)          // 2048 tokens

// ---------------- fp32 scratch ----------------
__device__ float g_xn   [MT*CD];
__device__ float g_xmean[CB*CD];
__device__ float g_hs   [CB*CDQ];
__device__ float g_coef [CB*CNC];
__device__ float g_cheby[MT*CD];
__device__ float g_q    [MT*CD];
__device__ float g_k    [MT*CD];
__device__ float g_v    [MT*CD];
__device__ float g_sc   [(size_t)CB*CAH*CS*CS];
__device__ float g_attn [MT*CD];
__device__ float g_slr  [MT*CD];
__device__ float g_gv   [MT*2*CD];

// ---------------- bf16 split scratch (3x K) ----------------
__device__ __align__(16) __nv_bfloat16 g3_xn  [MT*3*CD];
__device__ __align__(16) __nv_bfloat16 g3_kv  [MT*3*CD];
__device__ __align__(16) __nv_bfloat16 g3_attn[MT*3*CD];
__device__ __align__(16) __nv_bfloat16 g3_fus [MT*3*CD];
__device__ __align__(16) __nv_bfloat16 g3_hcat[(size_t)MT*3*2*CD];
__device__ __align__(16) __nv_bfloat16 g3_q   [MT*3*CD];
__device__ __align__(16) __nv_bfloat16 g3_k   [MT*3*CD];
__device__ __align__(16) __nv_bfloat16 g3_p   [(size_t)CB*CAH*CS*3*CS];   // 100MB split probs
__device__ __align__(16) __nv_bfloat16 g3_vt  [(size_t)CB*CAH*CAHD*3*CS]; // V^T split per head
__device__ __align__(16) __nv_bfloat16 g3_wq  [(size_t)CD*3*CD];
__device__ __align__(16) __nv_bfloat16 g3_wk  [(size_t)CD*3*CD];
__device__ __align__(16) __nv_bfloat16 g3_wv  [(size_t)CD*3*CD];
__device__ __align__(16) __nv_bfloat16 g3_wo  [(size_t)CD*3*CD];
__device__ __align__(16) __nv_bfloat16 g3_wout[(size_t)CD*3*CD];
__device__ __align__(16) __nv_bfloat16 g3_wfgv[(size_t)(2*CD)*3*(2*CD)];

// ---------------- helpers ----------------
__device__ __forceinline__ uint32_t smem_u32(const void* p) {
    uint32_t a;
    asm("{ .reg .u64 t; cvta.to.shared.u64 t, %1; cvt.u32.u64 %0, t; }" : "=r"(a) : "l"(p));
    return a;
}
__device__ __forceinline__ void cp16(uint32_t dst, const void* src) {
    asm volatile("cp.async.cg.shared.global [%0], [%1], 16;" :: "r"(dst), "l"(src) : "memory");
}
__device__ __forceinline__ void cp_commit() { asm volatile("cp.async.commit_group;" ::: "memory"); }

__device__ __forceinline__ void ldm_x4(uint32_t addr, uint32_t& r0, uint32_t& r1,
                                       uint32_t& r2, uint32_t& r3) {
    asm volatile("ldmatrix.sync.aligned.m8n8.x4.shared.b16 {%0,%1,%2,%3}, [%4];"
                 : "=r"(r0), "=r"(r1), "=r"(r2), "=r"(r3) : "r"(addr));
}
__device__ __forceinline__ void mma16816(float* c, const uint32_t* a, const uint32_t* b) {
    asm volatile("mma.sync.aligned.m16n8k16.row.col.f32.bf16.bf16.f32 "
                 "{%0,%1,%2,%3}, {%4,%5,%6,%7}, {%8,%9}, {%0,%1,%2,%3};"
                 : "+f"(c[0]), "+f"(c[1]), "+f"(c[2]), "+f"(c[3])
                 : "r"(a[0]), "r"(a[1]), "r"(a[2]), "r"(a[3]), "r"(b[0]), "r"(b[1]));
}

// ---------------- bf16 hi/lo split ----------------
__device__ __forceinline__ void split2(float a, __nv_bfloat16& hi, __nv_bfloat16& lo) {
    hi = __float2bfloat16(a);
    lo = __float2bfloat16(a - __bfloat162float(hi));
}

// ---------------- reductions ----------------
__device__ __forceinline__ float warpSum(float v) {
    #pragma unroll
    for (int o = 16; o > 0; o >>= 1) v += __shfl_xor_sync(0xffffffffu, v, o);
    return v;
}
__device__ __forceinline__ float warpMax(float v) {
    #pragma unroll
    for (int o = 16; o > 0; o >>= 1) v = fmaxf(v, __shfl_xor_sync(0xffffffffu, v, o));
    return v;
}
__device__ __forceinline__ float blockSum(float v) {
    __shared__ float sh[8];
    v = warpSum(v);
    __syncthreads();
    if ((threadIdx.x & 31) == 0) sh[threadIdx.x >> 5] = v;
    __syncthreads();
    float r = sh[0];
    #pragma unroll
    for (int i = 1; i < 8; i++) r += sh[i];
    return r;
}
__device__ __forceinline__ float blockMax(float v) {
    __shared__ float shm[8];
    v = warpMax(v);
    __syncthreads();
    if ((threadIdx.x & 31) == 0) shm[threadIdx.x >> 5] = v;
    __syncthreads();
    float r = shm[0];
    #pragma unroll
    for (int i = 1; i < 8; i++) r = fmaxf(r, shm[i]);
    return r;
}

// =================== HMMA bf16 GEMM: 128x128 tile, BK=32, 4-stage ==========
// A [M, lda] row-major bf16 (K contiguous); B [N, ldb] row-major bf16.
// C = alpha*A@B^T (+Add) fp32. Padded smem rows: 80-byte stride.
#define ROWB 80
#define TILEB (128*ROWB)     // 10240 per matrix
#define STGB  (2*TILEB)      // 20480 per stage
#define NSTG  4
#define MM_SMEM (NSTG*STGB)  // 81920

__global__ void __launch_bounds__(256, 2)
mm_bf16_kernel(const __nv_bfloat16* __restrict__ A, const __nv_bfloat16* __restrict__ B,
               float* __restrict__ C, const float* __restrict__ Add,
               int lda, int ldb, int ldc, int K3, float alpha,
               int bdiv, long long sAo, long long sAi, long long sBo, long long sBi,
               long long sCo, long long sCi) {
    extern __shared__ __align__(128) char sm[];

    int z = blockIdx.z, zo = z / bdiv, zi = z - zo * bdiv;
    A += zo * sAo + zi * sAi;
    B += zo * sBo + zi * sBi;
    long long coff = zo * sCo + zi * sCi;

    const int tid  = threadIdx.x, lane = tid & 31, wid = tid >> 5;
    const int wm   = wid >> 2, wn = wid & 3;           // 2 x 4 warps
    const int row0 = blockIdx.y * 128, col0 = blockIdx.x * 128;

    const uint32_t sbase = smem_u32(sm);
    const int lrow = tid >> 1;               // 0..127
    const int lch  = (tid & 1) * 2;          // 0 or 2 (16B chunks)

    const __nv_bfloat16* Agb = A + (long long)(row0 + lrow) * lda + lch * 8;
    const __nv_bfloat16* Bgb = B + (long long)(col0 + lrow) * ldb + lch * 8;
    const uint32_t sAw = sbase + lrow * ROWB + lch * 16;
    const uint32_t sBw = sAw + TILEB;

    auto load_stage = [&](int kc, int st) {
        uint32_t o = (uint32_t)st * STGB;
        const __nv_bfloat16* Ag = Agb + kc * 32;
        const __nv_bfloat16* Bg = Bgb + kc * 32;
        cp16(sAw + o,      Ag);
        cp16(sAw + o + 16, Ag + 8);
        cp16(sBw + o,      Bg);
        cp16(sBw + o + 16, Bg + 8);
        cp_commit();
    };

    float acc[4][4][4];
    #pragma unroll
    for (int i = 0; i < 4; i++)
        #pragma unroll
        for (int j = 0; j < 4; j++)
            #pragma unroll
            for (int e = 0; e < 4; e++) acc[i][j][e] = 0.f;

    const int NK = K3 / 32;
    load_stage(0, 0);
    load_stage(1, 1);
    load_stage(2, 2);

    const int lr15 = lane & 15, lhi = lane >> 4;
    const uint32_t aoff = (uint32_t)((wm * 64 + lr15) * ROWB + lhi * 16);
    const uint32_t boff = (uint32_t)((wn * 32 + lr15) * ROWB + lhi * 16) + TILEB;

    for (int kc = 0; kc < NK; kc++) {
        asm volatile("cp.async.wait_group 2;" ::: "memory");
        __syncthreads();
        if (kc + 3 < NK) load_stage(kc + 3, (kc + 3) & (NSTG - 1));
        else cp_commit();

        uint32_t sA = sbase + (uint32_t)(kc & (NSTG - 1)) * STGB + aoff;
        uint32_t sB = sbase + (uint32_t)(kc & (NSTG - 1)) * STGB + boff;
        #pragma unroll
        for (int ks = 0; ks < 2; ks++) {
            uint32_t a[4][4];
            #pragma unroll
            for (int mt = 0; mt < 4; mt++)
                ldm_x4(sA + mt * (16 * ROWB) + ks * 32, a[mt][0], a[mt][1], a[mt][2], a[mt][3]);
            uint32_t b[4][2];
            #pragma unroll
            for (int bt = 0; bt < 2; bt++) {
                uint32_t r0, r1, r2, r3;
                ldm_x4(sB + bt * (16 * ROWB) + ks * 32, r0, r1, r2, r3);
                b[bt * 2 + 0][0] = r0; b[bt * 2 + 0][1] = r2;
                b[bt * 2 + 1][0] = r1; b[bt * 2 + 1][1] = r3;
            }
            #pragma unroll
            for (int mt = 0; mt < 4; mt++)
                #pragma unroll
                for (int nt = 0; nt < 4; nt++)
                    mma16816(acc[mt][nt], a[mt], b[nt]);
        }
    }

    // ---- epilogue ----
    const int erow = row0 + wm * 64 + (lane >> 2);
    const int ecol = col0 + wn * 32 + (lane & 3) * 2;
    #pragma unroll
    for (int mt = 0; mt < 4; mt++) {
        #pragma unroll
        for (int half = 0; half < 2; half++) {
            long long r = (long long)(erow + mt * 16 + half * 8) * ldc + ecol + coff;
            #pragma unroll
            for (int nt = 0; nt < 4; nt++) {
                float2 v;
                v.x = acc[mt][nt][half * 2 + 0] * alpha;
                v.y = acc[mt][nt][half * 2 + 1] * alpha;
                if (Add) {
                    float2 ad = *(const float2*)(Add + r + nt * 8);
                    v.x += ad.x; v.y += ad.y;
                }
                *(float2*)(C + r + nt * 8) = v;
            }
        }
    }
}

// =================== elementwise / prep kernels ===================

__global__ void rmsnorm_split_kernel(const float* __restrict__ in, const float* __restrict__ w,
                                     float* __restrict__ outf, __nv_bfloat16* __restrict__ out3,
                                     int Ktot, int colofs) {
    long long row = blockIdx.x;
    const float* ip = in + row * CD;
    float vals[8], ss = 0.f;
    #pragma unroll
    for (int ii = 0; ii < 8; ii++) {
        float u = ip[threadIdx.x + ii * 256];
        vals[ii] = u; ss = fmaf(u, u, ss);
    }
    ss = blockSum(ss);
    float rs = rsqrtf(ss * (1.f / CD) + 1e-6f);
    long long b3 = row * 3LL * Ktot + colofs;
    #pragma unroll
    for (int ii = 0; ii < 8; ii++) {
        int i = threadIdx.x + ii * 256;
        float u = vals[ii] * rs * w[i];
        if (outf) outf[row * CD + i] = u;
        __nv_bfloat16 hi, lo; split2(u, hi, lo);
        out3[b3 + i] = hi;
        out3[b3 + Ktot + i] = hi;
        out3[b3 + 2 * Ktot + i] = lo;
    }
}

__global__ void colmean_kernel(const float* __restrict__ xn, float* __restrict__ xm) {
    int idx = blockIdx.x * blockDim.x + threadIdx.x;
    int b = idx / CD, d = idx % CD;
    float s = 0.f;
    for (int t = 0; t < CS; t++) s += xn[((long long)b * CS + t) * CD + d];
    xm[idx] = s * (1.f / CS);
}

__global__ void mlp2_kernel(const float* __restrict__ xm, const float* __restrict__ wc1,
                            const float* __restrict__ bc1, float* __restrict__ h) {
    int b = blockIdx.y, c = blockIdx.x * 256 + threadIdx.x;
    float s = 0.f;
    for (int k = 0; k < CD; k++) s = fmaf(xm[b * CD + k], wc1[(long long)k * CDQ + c], s);
    s += bc1[c];
    h[b * CDQ + c] = s / (1.f + expf(-s));
}

__global__ void coeff2_kernel(const float* __restrict__ h, const float* __restrict__ wc2,
                              const float* __restrict__ bc2, float* __restrict__ coef) {
    int b = blockIdx.y, c = blockIdx.x * 256 + threadIdx.x;
    float s = 0.f;
    for (int k = 0; k < CDQ; k++) s = fmaf(h[b * CDQ + k], wc2[(long long)k * CNC + c], s);
    s += bc2[c];
    int kdeg = (c / CHD) % CDEG;
    coef[(long long)b * CNC + c] = s * (0.1f / (float)(kdeg + 1));
}

__global__ void cheby2_kernel(const float* __restrict__ xn, const float* __restrict__ coef,
                              float* __restrict__ cheby, __nv_bfloat16* __restrict__ kv3) {
    long long bs = blockIdx.x;
    int b = (int)(bs / CS);
    int w = threadIdx.x >> 5, lane = threadIdx.x & 31;
    const float* u = xn + bs * CD + w * CHD;
    float s = 0.f;
    #pragma unroll
    for (int i = lane; i < CHD; i += 32) s += u[i];
    s = warpSum(s);
    float z = tanhf(s * (1.f / CHD));
    float T1 = z, T2 = 2.f * z * z - 1.f, T3 = 2.f * z * T2 - T1;
    const float* cp = coef + (((long long)b * CNH + w) * CDEG) * CHD;
    float* co = cheby + bs * CD + w * CHD;
    long long b3 = bs * (3LL * CD) + w * CHD;
    #pragma unroll
    for (int i = lane; i < CHD; i += 32) {
        float o = cp[i] + T1 * cp[CHD + i] + T2 * cp[2 * CHD + i] + T3 * cp[3 * CHD + i];
        co[i] = o;
        float val = u[i] + o;
        __nv_bfloat16 hi, lo; split2(val, hi, lo);
        kv3[b3 + i] = hi;
        kv3[b3 + CD + i] = hi;
        kv3[b3 + 2 * CD + i] = lo;
    }
}

// transpose + B-side split (hi,lo,hi): W[K,N] fp32 -> Y[N,3K] bf16
__global__ void transpose_split_kernel(const float* __restrict__ W, __nv_bfloat16* __restrict__ Y,
                                       int K, int N) {
    __shared__ float t[32][33];
    int k0 = blockIdx.y * 32, n0 = blockIdx.x * 32;
    int tx = threadIdx.x, ty = threadIdx.y;
    #pragma unroll
    for (int i = 0; i < 4; i++) {
        int k = k0 + ty + i * 8;
        t[ty + i * 8][tx] = W[(long long)k * N + n0 + tx];
    }
    __syncthreads();
    #pragma unroll
    for (int i = 0; i < 4; i++) {
        int n = n0 + ty + i * 8;
        int k = k0 + tx;
        float a = t[tx][ty + i * 8];
        __nv_bfloat16 hi, lo; split2(a, hi, lo);
        long long base = (long long)n * 3 * K;
        Y[base + k] = hi;
        Y[base + K + k] = lo;
        Y[base + 2 * K + k] = hi;
    }
}

// per-head V transpose + B-side split: v[M,2048] -> vt3[bh][n][3*512]
__global__ void vtrans_split_kernel(const float* __restrict__ v, __nv_bfloat16* __restrict__ vt3) {
    __shared__ float t[32][33];
    int bh = blockIdx.z, b = bh >> 4, h = bh & 15;
    int k0 = blockIdx.x * 32, n0 = blockIdx.y * 32;
    int tx = threadIdx.x, ty = threadIdx.y;
    #pragma unroll
    for (int i = 0; i < 4; i++) {
        int k = k0 + ty + i * 8;
        t[ty + i * 8][tx] = v[((long long)(b * CS + k)) * CD + h * CAHD + n0 + tx];
    }
    __syncthreads();
    #pragma unroll
    for (int i = 0; i < 4; i++) {
        int n = n0 + ty + i * 8;
        float a = t[tx][ty + i * 8];
        __nv_bfloat16 hi, lo; split2(a, hi, lo);
        long long base = ((long long)bh * CAHD + n) * (3 * CS);
        vt3[base + k0 + tx] = hi;
        vt3[base + CS + k0 + tx] = lo;
        vt3[base + 2 * CS + k0 + tx] = hi;
    }
}

__global__ void split_plain_kernel(const float* __restrict__ X, __nv_bfloat16* __restrict__ Y) {
    int m = blockIdx.y, c = blockIdx.x * 256 + threadIdx.x;
    float a = X[(long long)m * CD + c];
    __nv_bfloat16 hi, lo; split2(a, hi, lo);
    long long base = (long long)m * 3 * CD;
    Y[base + c] = hi;
    Y[base + CD + c] = hi;
    Y[base + 2 * CD + c] = lo;
}

// per-head split: X[M,2048] -> Y[M, 16*(3*128)]; bside: (hi,lo,hi) else (hi,hi,lo)
__global__ void split_heads_kernel(const float* __restrict__ X, __nv_bfloat16* __restrict__ Y,
                                   int bside) {
    int m = blockIdx.y, c = blockIdx.x * 256 + threadIdx.x;
    int h = c >> 7, d = c & 127;
    float a = X[(long long)m * CD + c];
    __nv_bfloat16 hi, lo; split2(a, hi, lo);
    long long base = (long long)m * (3 * CD) + (long long)h * 384;
    Y[base + d] = hi;
    Y[base + 128 + d] = bside ? lo : hi;
    Y[base + 256 + d] = bside ? hi : lo;
}

__global__ void fuse_split_kernel(const float* __restrict__ gv, const float* __restrict__ wnp,
                                  __nv_bfloat16* __restrict__ out3) {
    long long row = blockIdx.x;
    const float* gp = gv + row * (2 * CD);
    float t[8], ss = 0.f;
    #pragma unroll
    for (int ii = 0; ii < 8; ii++) {
        int i = threadIdx.x + ii * 256;
        float g = gp[i], v = gp[CD + i];
        float u = g / (1.f + expf(-g)) * v;
        t[ii] = u; ss = fmaf(u, u, ss);
    }
    ss = blockSum(ss);
    float rs = rsqrtf(ss * (1.f / CD) + 1e-6f);
    long long b3 = row * (3LL * CD);
    #pragma unroll
    for (int ii = 0; ii < 8; ii++) {
        int i = threadIdx.x + ii * 256;
        float u = t[ii] * rs * wnp[i];
        __nv_bfloat16 hi, lo; split2(u, hi, lo);
        out3[b3 + i] = hi;
        out3[b3 + CD + i] = hi;
        out3[b3 + 2 * CD + i] = lo;
    }
}

// ---- causal softmax over 512-wide rows; emits A-side split bf16 probs ----
__global__ void softmax_split_kernel(const float* __restrict__ sc, __nv_bfloat16* __restrict__ p3) {
    long long row = blockIdx.x;                   // (b,h,i) flattened
    int i = (int)(row % CS);
    const float* sp = sc + row * CS;
    float e[2];
    float m = -1e30f;
    #pragma unroll
    for (int t = 0; t < 2; t++) { int j = threadIdx.x + t * 256; if (j <= i) m = fmaxf(m, sp[j]); }
    m = blockMax(m);
    float s = 0.f;
    #pragma unroll
    for (int t = 0; t < 2; t++) {
        int j = threadIdx.x + t * 256;
        float ev = (j <= i) ? expf(sp[j] - m) : 0.f;
        e[t] = ev; s += ev;
    }
    s = blockSum(s);
    float inv = 1.f / s;
    long long b3 = row * (3LL * CS);
    #pragma unroll
    for (int t = 0; t < 2; t++) {
        int j = threadIdx.x + t * 256;
        float u = e[t] * inv;
        __nv_bfloat16 hi, lo; split2(u, hi, lo);
        p3[b3 + j] = hi;
        p3[b3 + CS + j] = hi;
        p3[b3 + 2 * CS + j] = lo;
    }
}

// ---------------- host ----------------
static void mm(const __nv_bfloat16* A, const __nv_bfloat16* B, float* C, const float* Add,
               int M, int N, int K3, int lda, int ldb, int ldc, float alpha,
               int bz, int bdiv, long long sAo, long long sAi, long long sBo, long long sBi,
               long long sCo, long long sCi) {
    dim3 grid(N / 128, M / 128, bz);
    mm_bf16_kernel<<<grid, 256, MM_SMEM>>>(A, B, C, Add, lda, ldb, ldc, K3, alpha,
                                           bdiv, sAo, sAi, sBo, sBi, sCo, sCi);
}

extern "C" void kernel_launch(void* const* d_in, const int* in_sizes, int n_in,
                              void* d_out, int out_size) {
    const float* x     = (const float*)d_in[0];
    const float* w_in  = (const float*)d_in[1];
    const float* wc1   = (const float*)d_in[6];
    const float* bc1   = (const float*)d_in[7];
    const float* wc2   = (const float*)d_in[8];
    const float* bc2   = (const float*)d_in[9];
    const float* wq    = (const float*)d_in[10];
    const float* wk    = (const float*)d_in[11];
    const float* wv    = (const float*)d_in[12];
    const float* wo    = (const float*)d_in[13];
    const float* w_nc  = (const float*)d_in[14];
    const float* w_ns  = (const float*)d_in[15];
    const float* w_fgv = (const float*)d_in[16];
    const float* w_np  = (const float*)d_in[17];
    const float* w_out = (const float*)d_in[18];
    float* out = (float*)d_out;

    cudaFuncSetAttribute(mm_bf16_kernel, cudaFuncAttributeMaxDynamicSharedMemorySize, MM_SMEM);

    float *xn, *xm, *hs, *coef, *cheb, *q, *k, *v, *sc, *attn, *slr, *gvb;
    cudaGetSymbolAddress((void**)&xn,   g_xn);
    cudaGetSymbolAddress((void**)&xm,   g_xmean);
    cudaGetSymbolAddress((void**)&hs,   g_hs);
    cudaGetSymbolAddress((void**)&coef, g_coef);
    cudaGetSymbolAddress((void**)&cheb, g_cheby);
    cudaGetSymbolAddress((void**)&q,    g_q);
    cudaGetSymbolAddress((void**)&k,    g_k);
    cudaGetSymbolAddress((void**)&v,    g_v);
    cudaGetSymbolAddress((void**)&sc,   g_sc);
    cudaGetSymbolAddress((void**)&attn, g_attn);
    cudaGetSymbolAddress((void**)&slr,  g_slr);
    cudaGetSymbolAddress((void**)&gvb,  g_gv);

    __nv_bfloat16 *xn3, *kv3, *attn3, *fus3, *hcat3, *q3, *k3, *p3, *vt3;
    __nv_bfloat16 *wq3, *wk3, *wv3, *wo3, *wout3, *wfgv3;
    cudaGetSymbolAddress((void**)&xn3,   g3_xn);
    cudaGetSymbolAddress((void**)&kv3,   g3_kv);
    cudaGetSymbolAddress((void**)&attn3, g3_attn);
    cudaGetSymbolAddress((void**)&fus3,  g3_fus);
    cudaGetSymbolAddress((void**)&hcat3, g3_hcat);
    cudaGetSymbolAddress((void**)&q3,    g3_q);
    cudaGetSymbolAddress((void**)&k3,    g3_k);
    cudaGetSymbolAddress((void**)&p3,    g3_p);
    cudaGetSymbolAddress((void**)&vt3,   g3_vt);
    cudaGetSymbolAddress((void**)&wq3,   g3_wq);
    cudaGetSymbolAddress((void**)&wk3,   g3_wk);
    cudaGetSymbolAddress((void**)&wv3,   g3_wv);
    cudaGetSymbolAddress((void**)&wo3,   g3_wo);
    cudaGetSymbolAddress((void**)&wout3, g3_wout);
    cudaGetSymbolAddress((void**)&wfgv3, g3_wfgv);

    // weight transposes + B-side splits
    dim3 tgrid(CD / 32, CD / 32), tblk(32, 8);
    transpose_split_kernel<<<tgrid, tblk>>>(wq,    wq3,   CD, CD);
    transpose_split_kernel<<<tgrid, tblk>>>(wk,    wk3,   CD, CD);
    transpose_split_kernel<<<tgrid, tblk>>>(wv,    wv3,   CD, CD);
    transpose_split_kernel<<<tgrid, tblk>>>(wo,    wo3,   CD, CD);
    transpose_split_kernel<<<tgrid, tblk>>>(w_out, wout3, CD, CD);
    dim3 tgrid2((2 * CD) / 32, (2 * CD) / 32);
    transpose_split_kernel<<<tgrid2, tblk>>>(w_fgv, wfgv3, 2 * CD, 2 * CD);

    // activations prep
    rmsnorm_split_kernel<<<MT, 256>>>(x, w_in, xn, xn3, CD, 0);
    colmean_kernel<<<(CB * CD) / 256, 256>>>(xn, xm);
    mlp2_kernel<<<dim3(CDQ / 256, CB), 256>>>(xm, wc1, bc1, hs);
    coeff2_kernel<<<dim3(CNC / 256, CB), 256>>>(hs, wc2, bc2, coef);
    cheby2_kernel<<<MT, 256>>>(xn, coef, cheb, kv3);

    // q/k/v projections (HMMA, 3-term split)
    mm(xn3, wq3, q, 0, MT, CD, 3 * CD, 3 * CD, 3 * CD, CD, 1.f, 1, 1, 0, 0, 0, 0, 0, 0);
    mm(kv3, wk3, k, 0, MT, CD, 3 * CD, 3 * CD, 3 * CD, CD, 1.f, 1, 1, 0, 0, 0, 0, 0, 0);
    mm(kv3, wv3, v, 0, MT, CD, 3 * CD, 3 * CD, 3 * CD, CD, 1.f, 1, 1, 0, 0, 0, 0, 0, 0);

    // per-head re-splits for attention
    split_heads_kernel<<<dim3(CD / 256, MT), 256>>>(q, q3, 0);
    split_heads_kernel<<<dim3(CD / 256, MT), 256>>>(k, k3, 1);
    vtrans_split_kernel<<<dim3(CS / 32, CAHD / 32, CB * CAH), tblk>>>(v, vt3);

    // scores = q @ k^T / sqrt(hd)  (batched over b,h)
    mm(q3, k3, sc, 0, CS, CS, 384, 3 * CD, 3 * CD, CS, 0.08838834764831845f,
       CB * CAH, CAH,
       (long long)CS * 3 * CD, 384,
       (long long)CS * 3 * CD, 384,
       (long long)CAH * CS * CS, (long long)CS * CS);

    // causal softmax -> split probs
    softmax_split_kernel<<<CB * CAH * CS, 256>>>(sc, p3);

    // attn = P @ V  (HMMA split, per head)
    mm(p3, vt3, attn, 0, CS, CAHD, 3 * CS, 3 * CS, 3 * CS, CD, 1.f,
       CB * CAH, CAH,
       (long long)CAH * CS * 3 * CS, (long long)CS * 3 * CS,
       (long long)CAH * CAHD * 3 * CS, (long long)CAHD * 3 * CS,
       (long long)CS * CD, CAHD);

    // slr = attn @ wo
    split_plain_kernel<<<dim3(CD / 256, MT), 256>>>(attn, attn3);
    mm(attn3, wo3, slr, 0, MT, CD, 3 * CD, 3 * CD, 3 * CD, CD, 1.f, 1, 1, 0, 0, 0, 0, 0, 0);

    // hcat3 = split([rmsnorm(cheb), rmsnorm(slr)])
    rmsnorm_split_kernel<<<MT, 256>>>(cheb, w_nc, 0, hcat3, 2 * CD, 0);
    rmsnorm_split_kernel<<<MT, 256>>>(slr,  w_ns, 0, hcat3, 2 * CD, CD);

    // gv = hcat @ w_fgv
    mm(hcat3, wfgv3, gvb, 0, MT, 2 * CD, 3 * 2 * CD, 3 * 2 * CD, 3 * 2 * CD, 2 * CD, 1.f,
       1, 1, 0, 0, 0, 0, 0, 0);

    // fused, then out = x + fused @ w_out
    fuse_split_kernel<<<MT, 256>>>(gvb, w_np, fus3);
    mm(fus3, wout3, out, x, MT, CD, 3 * CD, 3 * CD, 3 * CD, CD, 1.f, 1, 1, 0, 0, 0, 0, 0, 0);
}

// round 5
// speedup vs baseline: 1.7400x; 1.0355x over previous
#include <cuda_runtime.h>
#include <cuda_bf16.h>
#include <cstdint>
#include <math.h>

// ---------------- problem constants ----------------
#define CB   4
#define CS   512
#define CD   2048
#define CNH  8
#define CDEG 4
#define CHD  256
#define CAH  16
#define CAHD 128
#define CDQ  512
#define CNC  (CNH*CDEG*CHD)   // 8192
#define MT   (CB*CS)          // 2048 tokens

// ---------------- fp32 scratch ----------------
__device__ float g_xn   [MT*CD];
__device__ float g_xmean[CB*CD];
__device__ float g_hs   [CB*CDQ];
__device__ float g_coef [CB*CNC];
__device__ float g_cheby[MT*CD];
__device__ float g_v    [MT*CD];
__device__ float g_sc   [(size_t)CB*CAH*CS*CS];
__device__ float g_slr  [MT*CD];
__device__ float g_gv   [MT*2*CD];

// ---------------- bf16 split scratch (3x K) ----------------
__device__ __align__(16) __nv_bfloat16 g3_xn  [MT*3*CD];
__device__ __align__(16) __nv_bfloat16 g3_kv  [MT*3*CD];
__device__ __align__(16) __nv_bfloat16 g3_attn[MT*3*CD];
__device__ __align__(16) __nv_bfloat16 g3_fus [MT*3*CD];
__device__ __align__(16) __nv_bfloat16 g3_hcat[(size_t)MT*3*2*CD];
__device__ __align__(16) __nv_bfloat16 g3_q   [MT*3*CD];
__device__ __align__(16) __nv_bfloat16 g3_k   [MT*3*CD];
__device__ __align__(16) __nv_bfloat16 g3_p   [(size_t)CB*CAH*CS*3*CS];
__device__ __align__(16) __nv_bfloat16 g3_vt  [(size_t)CB*CAH*CAHD*3*CS];
__device__ __align__(16) __nv_bfloat16 g3_wq  [(size_t)CD*3*CD];
__device__ __align__(16) __nv_bfloat16 g3_wk  [(size_t)CD*3*CD];
__device__ __align__(16) __nv_bfloat16 g3_wv  [(size_t)CD*3*CD];
__device__ __align__(16) __nv_bfloat16 g3_wo  [(size_t)CD*3*CD];
__device__ __align__(16) __nv_bfloat16 g3_wout[(size_t)CD*3*CD];
__device__ __align__(16) __nv_bfloat16 g3_wfgv[(size_t)(2*CD)*3*(2*CD)];

// ---------------- helpers ----------------
__device__ __forceinline__ uint32_t smem_u32(const void* p) {
    uint32_t a;
    asm("{ .reg .u64 t; cvta.to.shared.u64 t, %1; cvt.u32.u64 %0, t; }" : "=r"(a) : "l"(p));
    return a;
}
__device__ __forceinline__ void cp16(uint32_t dst, const void* src) {
    asm volatile("cp.async.cg.shared.global [%0], [%1], 16;" :: "r"(dst), "l"(src) : "memory");
}
__device__ __forceinline__ void cp_commit() { asm volatile("cp.async.commit_group;" ::: "memory"); }

__device__ __forceinline__ void ldm_x4(uint32_t addr, uint32_t& r0, uint32_t& r1,
                                       uint32_t& r2, uint32_t& r3) {
    asm volatile("ldmatrix.sync.aligned.m8n8.x4.shared.b16 {%0,%1,%2,%3}, [%4];"
                 : "=r"(r0), "=r"(r1), "=r"(r2), "=r"(r3) : "r"(addr));
}
__device__ __forceinline__ void mma16816(float* c, const uint32_t* a, const uint32_t* b) {
    asm volatile("mma.sync.aligned.m16n8k16.row.col.f32.bf16.bf16.f32 "
                 "{%0,%1,%2,%3}, {%4,%5,%6,%7}, {%8,%9}, {%0,%1,%2,%3};"
                 : "+f"(c[0]), "+f"(c[1]), "+f"(c[2]), "+f"(c[3])
                 : "r"(a[0]), "r"(a[1]), "r"(a[2]), "r"(a[3]), "r"(b[0]), "r"(b[1]));
}

__device__ __forceinline__ void split2(float a, __nv_bfloat16& hi, __nv_bfloat16& lo) {
    hi = __float2bfloat16(a);
    lo = __float2bfloat16(a - __bfloat162float(hi));
}

// ---------------- reductions ----------------
__device__ __forceinline__ float warpSum(float v) {
    #pragma unroll
    for (int o = 16; o > 0; o >>= 1) v += __shfl_xor_sync(0xffffffffu, v, o);
    return v;
}
__device__ __forceinline__ float warpMax(float v) {
    #pragma unroll
    for (int o = 16; o > 0; o >>= 1) v = fmaxf(v, __shfl_xor_sync(0xffffffffu, v, o));
    return v;
}
__device__ __forceinline__ float blockSum(float v) {
    __shared__ float sh[8];
    v = warpSum(v);
    __syncthreads();
    if ((threadIdx.x & 31) == 0) sh[threadIdx.x >> 5] = v;
    __syncthreads();
    float r = sh[0];
    #pragma unroll
    for (int i = 1; i < 8; i++) r += sh[i];
    return r;
}
__device__ __forceinline__ float blockMax(float v) {
    __shared__ float shm[8];
    v = warpMax(v);
    __syncthreads();
    if ((threadIdx.x & 31) == 0) shm[threadIdx.x >> 5] = v;
    __syncthreads();
    float r = shm[0];
    #pragma unroll
    for (int i = 1; i < 8; i++) r = fmaxf(r, shm[i]);
    return r;
}

// =================== persistent HMMA bf16 GEMM ===================
// 128x128 tile, BK=32, 4-stage cp.async ring, tiles strided over grid.
// modes: 0 = fp32 C (+Add, alpha); 1 = q3 head split (hi,hi,lo);
//        2 = k3 head split (hi,lo,hi); 3 = attn3 token split from bh-batched PV.
#define ROWB 80
#define TILEB (128*ROWB)
#define STGB  (2*TILEB)
#define NSTG  4
#define MM_SMEM (NSTG*STGB)  // 81920

struct MMParams {
    const __nv_bfloat16* A;
    const __nv_bfloat16* B;
    float* C;
    const float* Add;
    __nv_bfloat16* S3;
    int lda, ldb, ldc, K3;
    float alpha;
    int bdiv;
    long long sAo, sAi, sBo, sBi, sCo, sCi;
    int tilesM, tilesN, total;
    int mode;
    int causal;
};

__global__ void __launch_bounds__(256, 2)
mm_bf16_kernel(MMParams p) {
    extern __shared__ __align__(128) char sm[];

    const int tid  = threadIdx.x, lane = tid & 31, wid = tid >> 5;
    const int wm   = wid >> 2, wn = wid & 3;
    const uint32_t sbase = smem_u32(sm);
    const int lrow = tid >> 1;
    const int lch  = (tid & 1) * 2;
    const uint32_t sAw = sbase + lrow * ROWB + lch * 16;
    const uint32_t sBw = sAw + TILEB;
    const int lr15 = lane & 15, lhi = lane >> 4;
    const uint32_t aoff = (uint32_t)((wm * 64 + lr15) * ROWB + lhi * 16);
    const uint32_t boff = (uint32_t)((wn * 32 + lr15) * ROWB + lhi * 16) + TILEB;
    const int tilesMN = p.tilesM * p.tilesN;
    const int NK = p.K3 / 32;

    for (int t = blockIdx.x; t < p.total; t += gridDim.x) {
        int z  = t / tilesMN;
        int r  = t - z * tilesMN;
        int ty = r / p.tilesN, tx = r - ty * p.tilesN;
        if (p.causal && tx > ty) continue;
        int zo = z / p.bdiv, zi = z - zo * p.bdiv;

        const __nv_bfloat16* Agb = p.A + zo * p.sAo + zi * p.sAi
                                   + (long long)(ty * 128 + lrow) * p.lda + lch * 8;
        const __nv_bfloat16* Bgb = p.B + zo * p.sBo + zi * p.sBi
                                   + (long long)(tx * 128 + lrow) * p.ldb + lch * 8;

        float acc[4][4][4];
        #pragma unroll
        for (int i = 0; i < 4; i++)
            #pragma unroll
            for (int j = 0; j < 4; j++)
                #pragma unroll
                for (int e = 0; e < 4; e++) acc[i][j][e] = 0.f;

        // preload 3 stages
        #pragma unroll
        for (int s = 0; s < 3; s++) {
            uint32_t o = (uint32_t)s * STGB;
            const __nv_bfloat16* Ag = Agb + s * 32;
            const __nv_bfloat16* Bg = Bgb + s * 32;
            cp16(sAw + o,      Ag);
            cp16(sAw + o + 16, Ag + 8);
            cp16(sBw + o,      Bg);
            cp16(sBw + o + 16, Bg + 8);
            cp_commit();
        }

        for (int kc = 0; kc < NK; kc++) {
            asm volatile("cp.async.wait_group 2;" ::: "memory");
            __syncthreads();
            if (kc + 3 < NK) {
                uint32_t o = (uint32_t)((kc + 3) & (NSTG - 1)) * STGB;
                const __nv_bfloat16* Ag = Agb + (kc + 3) * 32;
                const __nv_bfloat16* Bg = Bgb + (kc + 3) * 32;
                cp16(sAw + o,      Ag);
                cp16(sAw + o + 16, Ag + 8);
                cp16(sBw + o,      Bg);
                cp16(sBw + o + 16, Bg + 8);
            }
            cp_commit();

            uint32_t sA = sbase + (uint32_t)(kc & (NSTG - 1)) * STGB + aoff;
            uint32_t sB = sbase + (uint32_t)(kc & (NSTG - 1)) * STGB + boff;
            #pragma unroll
            for (int ks = 0; ks < 2; ks++) {
                uint32_t a[4][4];
                #pragma unroll
                for (int mt = 0; mt < 4; mt++)
                    ldm_x4(sA + mt * (16 * ROWB) + ks * 32, a[mt][0], a[mt][1], a[mt][2], a[mt][3]);
                uint32_t b[4][2];
                #pragma unroll
                for (int bt = 0; bt < 2; bt++) {
                    uint32_t r0, r1, r2, r3;
                    ldm_x4(sB + bt * (16 * ROWB) + ks * 32, r0, r1, r2, r3);
                    b[bt * 2 + 0][0] = r0; b[bt * 2 + 0][1] = r2;
                    b[bt * 2 + 1][0] = r1; b[bt * 2 + 1][1] = r3;
                }
                #pragma unroll
                for (int mt = 0; mt < 4; mt++)
                    #pragma unroll
                    for (int nt = 0; nt < 4; nt++)
                        mma16816(acc[mt][nt], a[mt], b[nt]);
            }
        }
        __syncthreads();   // all smem reads done before next tile's preloads

        // ---- epilogue ----
        const int row0 = ty * 128, col0 = tx * 128;
        const int erow = wm * 64 + (lane >> 2);
        const int ecol = wn * 32 + (lane & 3) * 2;

        if (p.mode == 0) {
            long long coff = zo * p.sCo + zi * p.sCi;
            #pragma unroll
            for (int mt = 0; mt < 4; mt++)
                #pragma unroll
                for (int half = 0; half < 2; half++) {
                    int gr = row0 + erow + mt * 16 + half * 8;
                    long long rb = (long long)gr * p.ldc + col0 + ecol + coff;
                    #pragma unroll
                    for (int nt = 0; nt < 4; nt++) {
                        float2 v;
                        v.x = acc[mt][nt][half * 2 + 0] * p.alpha;
                        v.y = acc[mt][nt][half * 2 + 1] * p.alpha;
                        if (p.Add) {
                            float2 ad = *(const float2*)(p.Add + rb + nt * 8);
                            v.x += ad.x; v.y += ad.y;
                        }
                        *(float2*)(p.C + rb + nt * 8) = v;
                    }
                }
        } else if (p.mode == 3) {
            // PV output -> attn3 token split (hi,hi,lo)
            int b = z >> 4, h = z & 15;
            #pragma unroll
            for (int mt = 0; mt < 4; mt++)
                #pragma unroll
                for (int half = 0; half < 2; half++) {
                    int gr = row0 + erow + mt * 16 + half * 8;     // 0..511
                    long long base = ((long long)(b * CS + gr)) * (3LL * CD)
                                     + h * CAHD + col0 + ecol;
                    #pragma unroll
                    for (int nt = 0; nt < 4; nt++) {
                        float v0 = acc[mt][nt][half * 2 + 0];
                        float v1 = acc[mt][nt][half * 2 + 1];
                        __nv_bfloat16 h0, l0, h1, l1;
                        split2(v0, h0, l0); split2(v1, h1, l1);
                        __nv_bfloat162 hh = __nv_bfloat162(h0, h1);
                        __nv_bfloat162 ll = __nv_bfloat162(l0, l1);
                        __nv_bfloat162* d0 = (__nv_bfloat162*)(p.S3 + base + nt * 8);
                        *(__nv_bfloat162*)((__nv_bfloat16*)d0 + 0)      = hh;
                        *(__nv_bfloat162*)((__nv_bfloat16*)d0 + CD)     = hh;
                        *(__nv_bfloat162*)((__nv_bfloat16*)d0 + 2 * CD) = ll;
                    }
                }
        } else {
            // per-head split: mode 1 (hi,hi,lo) / mode 2 (hi,lo,hi)
            #pragma unroll
            for (int mt = 0; mt < 4; mt++)
                #pragma unroll
                for (int half = 0; half < 2; half++) {
                    int gr = row0 + erow + mt * 16 + half * 8;     // token
                    long long rowb = (long long)gr * (3LL * CD);
                    #pragma unroll
                    for (int nt = 0; nt < 4; nt++) {
                        int n = col0 + ecol + nt * 8;
                        int hh_ = n >> 7, d = n & 127;
                        long long base = rowb + hh_ * 384 + d;
                        float v0 = acc[mt][nt][half * 2 + 0];
                        float v1 = acc[mt][nt][half * 2 + 1];
                        __nv_bfloat16 h0, l0, h1, l1;
                        split2(v0, h0, l0); split2(v1, h1, l1);
                        __nv_bfloat162 hv = __nv_bfloat162(h0, h1);
                        __nv_bfloat162 lv = __nv_bfloat162(l0, l1);
                        __nv_bfloat16* dp = p.S3 + base;
                        *(__nv_bfloat162*)(dp)       = hv;
                        *(__nv_bfloat162*)(dp + 128) = (p.mode == 1) ? hv : lv;
                        *(__nv_bfloat162*)(dp + 256) = (p.mode == 1) ? lv : hv;
                    }
                }
        }
    }
}

// =================== elementwise / prep kernels ===================

__global__ void rmsnorm_split_kernel(const float* __restrict__ in, const float* __restrict__ w,
                                     float* __restrict__ outf, __nv_bfloat16* __restrict__ out3,
                                     int Ktot, int colofs) {
    long long row = blockIdx.x;
    const float* ip = in + row * CD;
    float vals[8], ss = 0.f;
    #pragma unroll
    for (int ii = 0; ii < 8; ii++) {
        float u = ip[threadIdx.x + ii * 256];
        vals[ii] = u; ss = fmaf(u, u, ss);
    }
    ss = blockSum(ss);
    float rs = rsqrtf(ss * (1.f / CD) + 1e-6f);
    long long b3 = row * 3LL * Ktot + colofs;
    #pragma unroll
    for (int ii = 0; ii < 8; ii++) {
        int i = threadIdx.x + ii * 256;
        float u = vals[ii] * rs * w[i];
        if (outf) outf[row * CD + i] = u;
        __nv_bfloat16 hi, lo; split2(u, hi, lo);
        out3[b3 + i] = hi;
        out3[b3 + Ktot + i] = hi;
        out3[b3 + 2 * Ktot + i] = lo;
    }
}

__global__ void colmean_kernel(const float* __restrict__ xn, float* __restrict__ xm) {
    int idx = blockIdx.x * blockDim.x + threadIdx.x;
    int b = idx / CD, d = idx % CD;
    float s = 0.f;
    for (int t = 0; t < CS; t++) s += xn[((long long)b * CS + t) * CD + d];
    xm[idx] = s * (1.f / CS);
}

__global__ void mlp2_kernel(const float* __restrict__ xm, const float* __restrict__ wc1,
                            const float* __restrict__ bc1, float* __restrict__ h) {
    int b = blockIdx.y, c = blockIdx.x * 256 + threadIdx.x;
    float s = 0.f;
    for (int k = 0; k < CD; k++) s = fmaf(xm[b * CD + k], wc1[(long long)k * CDQ + c], s);
    s += bc1[c];
    h[b * CDQ + c] = s / (1.f + expf(-s));
}

__global__ void coeff2_kernel(const float* __restrict__ h, const float* __restrict__ wc2,
                              const float* __restrict__ bc2, float* __restrict__ coef) {
    int b = blockIdx.y, c = blockIdx.x * 256 + threadIdx.x;
    float s = 0.f;
    for (int k = 0; k < CDQ; k++) s = fmaf(h[b * CDQ + k], wc2[(long long)k * CNC + c], s);
    s += bc2[c];
    int kdeg = (c / CHD) % CDEG;
    coef[(long long)b * CNC + c] = s * (0.1f / (float)(kdeg + 1));
}

__global__ void cheby2_kernel(const float* __restrict__ xn, const float* __restrict__ coef,
                              float* __restrict__ cheby, __nv_bfloat16* __restrict__ kv3) {
    long long bs = blockIdx.x;
    int b = (int)(bs / CS);
    int w = threadIdx.x >> 5, lane = threadIdx.x & 31;
    const float* u = xn + bs * CD + w * CHD;
    float s = 0.f;
    #pragma unroll
    for (int i = lane; i < CHD; i += 32) s += u[i];
    s = warpSum(s);
    float z = tanhf(s * (1.f / CHD));
    float T1 = z, T2 = 2.f * z * z - 1.f, T3 = 2.f * z * T2 - T1;
    const float* cp = coef + (((long long)b * CNH + w) * CDEG) * CHD;
    float* co = cheby + bs * CD + w * CHD;
    long long b3 = bs * (3LL * CD) + w * CHD;
    #pragma unroll
    for (int i = lane; i < CHD; i += 32) {
        float o = cp[i] + T1 * cp[CHD + i] + T2 * cp[2 * CHD + i] + T3 * cp[3 * CHD + i];
        co[i] = o;
        float val = u[i] + o;
        __nv_bfloat16 hi, lo; split2(val, hi, lo);
        kv3[b3 + i] = hi;
        kv3[b3 + CD + i] = hi;
        kv3[b3 + 2 * CD + i] = lo;
    }
}

// transpose + B-side split (hi,lo,hi): W[K,N] fp32 -> Y[N,3K] bf16
__global__ void transpose_split_kernel(const float* __restrict__ W, __nv_bfloat16* __restrict__ Y,
                                       int K, int N) {
    __shared__ float t[32][33];
    int k0 = blockIdx.y * 32, n0 = blockIdx.x * 32;
    int tx = threadIdx.x, ty = threadIdx.y;
    #pragma unroll
    for (int i = 0; i < 4; i++) {
        int k = k0 + ty + i * 8;
        t[ty + i * 8][tx] = W[(long long)k * N + n0 + tx];
    }
    __syncthreads();
    #pragma unroll
    for (int i = 0; i < 4; i++) {
        int n = n0 + ty + i * 8;
        int k = k0 + tx;
        float a = t[tx][ty + i * 8];
        __nv_bfloat16 hi, lo; split2(a, hi, lo);
        long long base = (long long)n * 3 * K;
        Y[base + k] = hi;
        Y[base + K + k] = lo;
        Y[base + 2 * K + k] = hi;
    }
}

// per-head V transpose + B-side split: v[M,2048] -> vt3[bh][n][3*512]
__global__ void vtrans_split_kernel(const float* __restrict__ v, __nv_bfloat16* __restrict__ vt3) {
    __shared__ float t[32][33];
    int bh = blockIdx.z, b = bh >> 4, h = bh & 15;
    int k0 = blockIdx.x * 32, n0 = blockIdx.y * 32;
    int tx = threadIdx.x, ty = threadIdx.y;
    #pragma unroll
    for (int i = 0; i < 4; i++) {
        int k = k0 + ty + i * 8;
        t[ty + i * 8][tx] = v[((long long)(b * CS + k)) * CD + h * CAHD + n0 + tx];
    }
    __syncthreads();
    #pragma unroll
    for (int i = 0; i < 4; i++) {
        int n = n0 + ty + i * 8;
        float a = t[tx][ty + i * 8];
        __nv_bfloat16 hi, lo; split2(a, hi, lo);
        long long base = ((long long)bh * CAHD + n) * (3 * CS);
        vt3[base + k0 + tx] = hi;
        vt3[base + CS + k0 + tx] = lo;
        vt3[base + 2 * CS + k0 + tx] = hi;
    }
}

__global__ void fuse_split_kernel(const float* __restrict__ gv, const float* __restrict__ wnp,
                                  __nv_bfloat16* __restrict__ out3) {
    long long row = blockIdx.x;
    const float* gp = gv + row * (2 * CD);
    float t[8], ss = 0.f;
    #pragma unroll
    for (int ii = 0; ii < 8; ii++) {
        int i = threadIdx.x + ii * 256;
        float g = gp[i], v = gp[CD + i];
        float u = g / (1.f + expf(-g)) * v;
        t[ii] = u; ss = fmaf(u, u, ss);
    }
    ss = blockSum(ss);
    float rs = rsqrtf(ss * (1.f / CD) + 1e-6f);
    long long b3 = row * (3LL * CD);
    #pragma unroll
    for (int ii = 0; ii < 8; ii++) {
        int i = threadIdx.x + ii * 256;
        float u = t[ii] * rs * wnp[i];
        __nv_bfloat16 hi, lo; split2(u, hi, lo);
        out3[b3 + i] = hi;
        out3[b3 + CD + i] = hi;
        out3[b3 + 2 * CD + i] = lo;
    }
}

// ---- causal softmax over 512-wide rows; emits A-side split bf16 probs ----
__global__ void softmax_split_kernel(const float* __restrict__ sc, __nv_bfloat16* __restrict__ p3) {
    long long row = blockIdx.x;
    int i = (int)(row % CS);
    const float* sp = sc + row * CS;
    float e[2];
    float m = -1e30f;
    #pragma unroll
    for (int t = 0; t < 2; t++) { int j = threadIdx.x + t * 256; if (j <= i) m = fmaxf(m, sp[j]); }
    m = blockMax(m);
    float s = 0.f;
    #pragma unroll
    for (int t = 0; t < 2; t++) {
        int j = threadIdx.x + t * 256;
        float ev = (j <= i) ? expf(sp[j] - m) : 0.f;
        e[t] = ev; s += ev;
    }
    s = blockSum(s);
    float inv = 1.f / s;
    long long b3 = row * (3LL * CS);
    #pragma unroll
    for (int t = 0; t < 2; t++) {
        int j = threadIdx.x + t * 256;
        float u = e[t] * inv;
        __nv_bfloat16 hi, lo; split2(u, hi, lo);
        p3[b3 + j] = hi;
        p3[b3 + CS + j] = hi;
        p3[b3 + 2 * CS + j] = lo;
    }
}

// ---------------- host ----------------
static int g_grid = 296;

static void mm(const __nv_bfloat16* A, const __nv_bfloat16* B, float* C, const float* Add,
               __nv_bfloat16* S3, int M, int N, int K3, int lda, int ldb, int ldc, float alpha,
               int bz, int bdiv, long long sAo, long long sAi, long long sBo, long long sBi,
               long long sCo, long long sCi, int mode, int causal) {
    MMParams p;
    p.A = A; p.B = B; p.C = C; p.Add = Add; p.S3 = S3;
    p.lda = lda; p.ldb = ldb; p.ldc = ldc; p.K3 = K3; p.alpha = alpha;
    p.bdiv = bdiv; p.sAo = sAo; p.sAi = sAi; p.sBo = sBo; p.sBi = sBi;
    p.sCo = sCo; p.sCi = sCi;
    p.tilesM = M / 128; p.tilesN = N / 128;
    p.total = bz * p.tilesM * p.tilesN;
    p.mode = mode; p.causal = causal;
    int grid = g_grid < p.total ? g_grid : p.total;
    mm_bf16_kernel<<<grid, 256, MM_SMEM>>>(p);
}

extern "C" void kernel_launch(void* const* d_in, const int* in_sizes, int n_in,
                              void* d_out, int out_size) {
    const float* x     = (const float*)d_in[0];
    const float* w_in  = (const float*)d_in[1];
    const float* wc1   = (const float*)d_in[6];
    const float* bc1   = (const float*)d_in[7];
    const float* wc2   = (const float*)d_in[8];
    const float* bc2   = (const float*)d_in[9];
    const float* wq    = (const float*)d_in[10];
    const float* wk    = (const float*)d_in[11];
    const float* wv    = (const float*)d_in[12];
    const float* wo    = (const float*)d_in[13];
    const float* w_nc  = (const float*)d_in[14];
    const float* w_ns  = (const float*)d_in[15];
    const float* w_fgv = (const float*)d_in[16];
    const float* w_np  = (const float*)d_in[17];
    const float* w_out = (const float*)d_in[18];
    float* out = (float*)d_out;

    int smc = 148;
    cudaDeviceGetAttribute(&smc, cudaDevAttrMultiProcessorCount, 0);
    g_grid = 2 * smc;

    cudaFuncSetAttribute(mm_bf16_kernel, cudaFuncAttributeMaxDynamicSharedMemorySize, MM_SMEM);

    float *xn, *xm, *hs, *coef, *cheb, *v, *sc, *slr, *gvb;
    cudaGetSymbolAddress((void**)&xn,   g_xn);
    cudaGetSymbolAddress((void**)&xm,   g_xmean);
    cudaGetSymbolAddress((void**)&hs,   g_hs);
    cudaGetSymbolAddress((void**)&coef, g_coef);
    cudaGetSymbolAddress((void**)&cheb, g_cheby);
    cudaGetSymbolAddress((void**)&v,    g_v);
    cudaGetSymbolAddress((void**)&sc,   g_sc);
    cudaGetSymbolAddress((void**)&slr,  g_slr);
    cudaGetSymbolAddress((void**)&gvb,  g_gv);

    __nv_bfloat16 *xn3, *kv3, *attn3, *fus3, *hcat3, *q3, *k3, *p3, *vt3;
    __nv_bfloat16 *wq3, *wk3, *wv3, *wo3, *wout3, *wfgv3;
    cudaGetSymbolAddress((void**)&xn3,   g3_xn);
    cudaGetSymbolAddress((void**)&kv3,   g3_kv);
    cudaGetSymbolAddress((void**)&attn3, g3_attn);
    cudaGetSymbolAddress((void**)&fus3,  g3_fus);
    cudaGetSymbolAddress((void**)&hcat3, g3_hcat);
    cudaGetSymbolAddress((void**)&q3,    g3_q);
    cudaGetSymbolAddress((void**)&k3,    g3_k);
    cudaGetSymbolAddress((void**)&p3,    g3_p);
    cudaGetSymbolAddress((void**)&vt3,   g3_vt);
    cudaGetSymbolAddress((void**)&wq3,   g3_wq);
    cudaGetSymbolAddress((void**)&wk3,   g3_wk);
    cudaGetSymbolAddress((void**)&wv3,   g3_wv);
    cudaGetSymbolAddress((void**)&wo3,   g3_wo);
    cudaGetSymbolAddress((void**)&wout3, g3_wout);
    cudaGetSymbolAddress((void**)&wfgv3, g3_wfgv);

    // weight transposes + B-side splits
    dim3 tgrid(CD / 32, CD / 32), tblk(32, 8);
    transpose_split_kernel<<<tgrid, tblk>>>(wq,    wq3,   CD, CD);
    transpose_split_kernel<<<tgrid, tblk>>>(wk,    wk3,   CD, CD);
    transpose_split_kernel<<<tgrid, tblk>>>(wv,    wv3,   CD, CD);
    transpose_split_kernel<<<tgrid, tblk>>>(wo,    wo3,   CD, CD);
    transpose_split_kernel<<<tgrid, tblk>>>(w_out, wout3, CD, CD);
    dim3 tgrid2((2 * CD) / 32, (2 * CD) / 32);
    transpose_split_kernel<<<tgrid2, tblk>>>(w_fgv, wfgv3, 2 * CD, 2 * CD);

    // activations prep
    rmsnorm_split_kernel<<<MT, 256>>>(x, w_in, xn, xn3, CD, 0);
    colmean_kernel<<<(CB * CD) / 256, 256>>>(xn, xm);
    mlp2_kernel<<<dim3(CDQ / 256, CB), 256>>>(xm, wc1, bc1, hs);
    coeff2_kernel<<<dim3(CNC / 256, CB), 256>>>(hs, wc2, bc2, coef);
    cheby2_kernel<<<MT, 256>>>(xn, coef, cheb, kv3);

    // q/k projections -> head-split epilogues; v -> fp32
    mm(xn3, wq3, 0, 0, q3, MT, CD, 3 * CD, 3 * CD, 3 * CD, CD, 1.f,
       1, 1, 0, 0, 0, 0, 0, 0, 1, 0);
    mm(kv3, wk3, 0, 0, k3, MT, CD, 3 * CD, 3 * CD, 3 * CD, CD, 1.f,
       1, 1, 0, 0, 0, 0, 0, 0, 2, 0);
    mm(kv3, wv3, v, 0, 0, MT, CD, 3 * CD, 3 * CD, 3 * CD, CD, 1.f,
       1, 1, 0, 0, 0, 0, 0, 0, 0, 0);

    vtrans_split_kernel<<<dim3(CS / 32, CAHD / 32, CB * CAH), tblk>>>(v, vt3);

    // scores = q @ k^T / sqrt(hd)  (batched over b,h) with causal tile skip
    mm(q3, k3, sc, 0, 0, CS, CS, 384, 3 * CD, 3 * CD, CS, 0.08838834764831845f,
       CB * CAH, CAH,
       (long long)CS * 3 * CD, 384,
       (long long)CS * 3 * CD, 384,
       (long long)CAH * CS * CS, (long long)CS * CS, 0, 1);

    softmax_split_kernel<<<CB * CAH * CS, 256>>>(sc, p3);

    // attn = P @ V -> attn3 split epilogue
    mm(p3, vt3, 0, 0, attn3, CS, CAHD, 3 * CS, 3 * CS, 3 * CS, CD, 1.f,
       CB * CAH, CAH,
       (long long)CAH * CS * 3 * CS, (long long)CS * 3 * CS,
       (long long)CAH * CAHD * 3 * CS, (long long)CAHD * 3 * CS,
       0, 0, 3, 0);

    // slr = attn @ wo
    mm(attn3, wo3, slr, 0, 0, MT, CD, 3 * CD, 3 * CD, 3 * CD, CD, 1.f,
       1, 1, 0, 0, 0, 0, 0, 0, 0, 0);

    // hcat3 = split([rmsnorm(cheb), rmsnorm(slr)])
    rmsnorm_split_kernel<<<MT, 256>>>(cheb, w_nc, 0, hcat3, 2 * CD, 0);
    rmsnorm_split_kernel<<<MT, 256>>>(slr,  w_ns, 0, hcat3, 2 * CD, CD);

    // gv = hcat @ w_fgv
    mm(hcat3, wfgv3, gvb, 0, 0, MT, 2 * CD, 3 * 2 * CD, 3 * 2 * CD, 3 * 2 * CD, 2 * CD, 1.f,
       1, 1, 0, 0, 0, 0, 0, 0, 0, 0);

    // fused, then out = x + fused @ w_out
    fuse_split_kernel<<<MT, 256>>>(gvb, w_np, fus3);
    mm(fus3, wout3, out, x, 0, MT, CD, 3 * CD, 3 * CD, 3 * CD, CD, 1.f,
       1, 1, 0, 0, 0, 0, 0, 0, 0, 0);
}

// round 6
// speedup vs baseline: 2.0166x; 1.1590x over previous
#include <cuda_runtime.h>
#include <cuda_bf16.h>
#include <cstdint>
#include <math.h>

// ---------------- problem constants ----------------
#define CB   4
#define CS   512
#define CD   2048
#define CNH  8
#define CDEG 4
#define CHD  256
#define CAH  16
#define CAHD 128
#define CDQ  512
#define CNC  (CNH*CDEG*CHD)   // 8192
#define MT   (CB*CS)          // 2048 tokens

// ---------------- fp32 scratch ----------------
__device__ float g_xn   [MT*CD];
__device__ float g_xmean[CB*CD];
__device__ float g_hs   [CB*CDQ];
__device__ float g_coef [CB*CNC];
__device__ float g_v    [MT*CD];
__device__ float g_sc   [(size_t)CB*CAH*CS*CS];
__device__ float g_slr  [MT*CD];
__device__ float g_gv   [MT*2*CD];
__device__ float g_cw1  [(size_t)8*128*(2*CD)];     // CW1 [h][row][4096]

// ---------------- bf16 split scratch (3x K) ----------------
__device__ __align__(16) __nv_bfloat16 g3_xn   [MT*3*CD];
__device__ __align__(16) __nv_bfloat16 g3_kv   [MT*3*CD];
__device__ __align__(16) __nv_bfloat16 g3_attn [MT*3*CD];
__device__ __align__(16) __nv_bfloat16 g3_fus  [MT*3*CD];
__device__ __align__(16) __nv_bfloat16 g3_h2   [(size_t)MT*3*CD];         // split rmsnorm(slr)
__device__ __align__(16) __nv_bfloat16 g3_q    [MT*3*CD];
__device__ __align__(16) __nv_bfloat16 g3_k    [MT*3*CD];
__device__ __align__(16) __nv_bfloat16 g3_p    [(size_t)CB*CAH*CS*3*CS];
__device__ __align__(16) __nv_bfloat16 g3_vt   [(size_t)CB*CAH*CAHD*3*CS];
__device__ __align__(16) __nv_bfloat16 g3_wq   [(size_t)CD*3*CD];
__device__ __align__(16) __nv_bfloat16 g3_wk   [(size_t)CD*3*CD];
__device__ __align__(16) __nv_bfloat16 g3_wv   [(size_t)CD*3*CD];
__device__ __align__(16) __nv_bfloat16 g3_wo   [(size_t)CD*3*CD];
__device__ __align__(16) __nv_bfloat16 g3_wout [(size_t)CD*3*CD];
__device__ __align__(16) __nv_bfloat16 g3_wfgvb[(size_t)(2*CD)*3*CD];     // bottom half, [4096][6144]
__device__ __align__(16) __nv_bfloat16 g3_wt1  [(size_t)8*(2*CD)*768];    // top half per head [h][4096][768]
__device__ __align__(16) __nv_bfloat16 g3_cf   [(size_t)8*128*768];       // coeff3 padded [h][128][768]
__device__ __align__(16) __nv_bfloat16 g3_cw1t [(size_t)CB*(2*CD)*96];    // CW1^T split [b][4096][96]
__device__ __align__(16) __nv_bfloat16 g3_tsc  [(size_t)MT*96];           // rs*T split [token][96]

// ---------------- helpers ----------------
__device__ __forceinline__ uint32_t smem_u32(const void* p) {
    uint32_t a;
    asm("{ .reg .u64 t; cvta.to.shared.u64 t, %1; cvt.u32.u64 %0, t; }" : "=r"(a) : "l"(p));
    return a;
}
__device__ __forceinline__ void cp16(uint32_t dst, const void* src) {
    asm volatile("cp.async.cg.shared.global [%0], [%1], 16;" :: "r"(dst), "l"(src) : "memory");
}
__device__ __forceinline__ void cp_commit() { asm volatile("cp.async.commit_group;" ::: "memory"); }

__device__ __forceinline__ void ldm_x4(uint32_t addr, uint32_t& r0, uint32_t& r1,
                                       uint32_t& r2, uint32_t& r3) {
    asm volatile("ldmatrix.sync.aligned.m8n8.x4.shared.b16 {%0,%1,%2,%3}, [%4];"
                 : "=r"(r0), "=r"(r1), "=r"(r2), "=r"(r3) : "r"(addr));
}
__device__ __forceinline__ void mma16816(float* c, const uint32_t* a, const uint32_t* b) {
    asm volatile("mma.sync.aligned.m16n8k16.row.col.f32.bf16.bf16.f32 "
                 "{%0,%1,%2,%3}, {%4,%5,%6,%7}, {%8,%9}, {%0,%1,%2,%3};"
                 : "+f"(c[0]), "+f"(c[1]), "+f"(c[2]), "+f"(c[3])
                 : "r"(a[0]), "r"(a[1]), "r"(a[2]), "r"(a[3]), "r"(b[0]), "r"(b[1]));
}

__device__ __forceinline__ void split2(float a, __nv_bfloat16& hi, __nv_bfloat16& lo) {
    hi = __float2bfloat16(a);
    lo = __float2bfloat16(a - __bfloat162float(hi));
}

// ---------------- reductions ----------------
__device__ __forceinline__ float warpSum(float v) {
    #pragma unroll
    for (int o = 16; o > 0; o >>= 1) v += __shfl_xor_sync(0xffffffffu, v, o);
    return v;
}
__device__ __forceinline__ float warpMax(float v) {
    #pragma unroll
    for (int o = 16; o > 0; o >>= 1) v = fmaxf(v, __shfl_xor_sync(0xffffffffu, v, o));
    return v;
}
__device__ __forceinline__ float blockSum(float v) {
    __shared__ float sh[8];
    v = warpSum(v);
    __syncthreads();
    if ((threadIdx.x & 31) == 0) sh[threadIdx.x >> 5] = v;
    __syncthreads();
    float r = sh[0];
    #pragma unroll
    for (int i = 1; i < 8; i++) r += sh[i];
    return r;
}
__device__ __forceinline__ float blockMax(float v) {
    __shared__ float shm[8];
    v = warpMax(v);
    __syncthreads();
    if ((threadIdx.x & 31) == 0) shm[threadIdx.x >> 5] = v;
    __syncthreads();
    float r = shm[0];
    #pragma unroll
    for (int i = 1; i < 8; i++) r = fmaxf(r, shm[i]);
    return r;
}

// =================== persistent HMMA bf16 GEMM ===================
#define ROWB 80
#define TILEB (128*ROWB)
#define STGB  (2*TILEB)
#define NSTG  4
#define MM_SMEM (NSTG*STGB)  // 81920

struct MMParams {
    const __nv_bfloat16* A;
    const __nv_bfloat16* B;
    float* C;
    const float* Add;
    __nv_bfloat16* S3;
    int lda, ldb, ldc, K3;
    float alpha;
    int bdiv;
    long long sAo, sAi, sBo, sBi, sCo, sCi;
    int tilesM, tilesN, total;
    int mode;        // 0 fp32 C(+Add); 1 q3 split; 2 k3 split; 3 attn3 split
    int causal;
};

__global__ void __launch_bounds__(256, 2)
mm_bf16_kernel(MMParams p) {
    extern __shared__ __align__(128) char sm[];

    const int tid  = threadIdx.x, lane = tid & 31, wid = tid >> 5;
    const int wm   = wid >> 2, wn = wid & 3;
    const uint32_t sbase = smem_u32(sm);
    const int lrow = tid >> 1;
    const int lch  = (tid & 1) * 2;
    const uint32_t sAw = sbase + lrow * ROWB + lch * 16;
    const uint32_t sBw = sAw + TILEB;
    const int lr15 = lane & 15, lhi = lane >> 4;
    const uint32_t aoff = (uint32_t)((wm * 64 + lr15) * ROWB + lhi * 16);
    const uint32_t boff = (uint32_t)((wn * 32 + lr15) * ROWB + lhi * 16) + TILEB;
    const int tilesMN = p.tilesM * p.tilesN;
    const int NK = p.K3 / 32;

    for (int t = blockIdx.x; t < p.total; t += gridDim.x) {
        int z  = t / tilesMN;
        int r  = t - z * tilesMN;
        int ty = r / p.tilesN, tx = r - ty * p.tilesN;
        if (p.causal && tx > ty) continue;
        int zo = z / p.bdiv, zi = z - zo * p.bdiv;

        const __nv_bfloat16* Agb = p.A + zo * p.sAo + zi * p.sAi
                                   + (long long)(ty * 128 + lrow) * p.lda + lch * 8;
        const __nv_bfloat16* Bgb = p.B + zo * p.sBo + zi * p.sBi
                                   + (long long)(tx * 128 + lrow) * p.ldb + lch * 8;

        float acc[4][4][4];
        #pragma unroll
        for (int i = 0; i < 4; i++)
            #pragma unroll
            for (int j = 0; j < 4; j++)
                #pragma unroll
                for (int e = 0; e < 4; e++) acc[i][j][e] = 0.f;

        #pragma unroll
        for (int s = 0; s < 3; s++) {
            uint32_t o = (uint32_t)s * STGB;
            const __nv_bfloat16* Ag = Agb + s * 32;
            const __nv_bfloat16* Bg = Bgb + s * 32;
            cp16(sAw + o,      Ag);
            cp16(sAw + o + 16, Ag + 8);
            cp16(sBw + o,      Bg);
            cp16(sBw + o + 16, Bg + 8);
            cp_commit();
        }

        for (int kc = 0; kc < NK; kc++) {
            asm volatile("cp.async.wait_group 2;" ::: "memory");
            __syncthreads();
            if (kc + 3 < NK) {
                uint32_t o = (uint32_t)((kc + 3) & (NSTG - 1)) * STGB;
                const __nv_bfloat16* Ag = Agb + (kc + 3) * 32;
                const __nv_bfloat16* Bg = Bgb + (kc + 3) * 32;
                cp16(sAw + o,      Ag);
                cp16(sAw + o + 16, Ag + 8);
                cp16(sBw + o,      Bg);
                cp16(sBw + o + 16, Bg + 8);
            }
            cp_commit();

            uint32_t sA = sbase + (uint32_t)(kc & (NSTG - 1)) * STGB + aoff;
            uint32_t sB = sbase + (uint32_t)(kc & (NSTG - 1)) * STGB + boff;
            #pragma unroll
            for (int ks = 0; ks < 2; ks++) {
                uint32_t a[4][4];
                #pragma unroll
                for (int mt = 0; mt < 4; mt++)
                    ldm_x4(sA + mt * (16 * ROWB) + ks * 32, a[mt][0], a[mt][1], a[mt][2], a[mt][3]);
                uint32_t b[4][2];
                #pragma unroll
                for (int bt = 0; bt < 2; bt++) {
                    uint32_t r0, r1, r2, r3;
                    ldm_x4(sB + bt * (16 * ROWB) + ks * 32, r0, r1, r2, r3);
                    b[bt * 2 + 0][0] = r0; b[bt * 2 + 0][1] = r2;
                    b[bt * 2 + 1][0] = r1; b[bt * 2 + 1][1] = r3;
                }
                #pragma unroll
                for (int mt = 0; mt < 4; mt++)
                    #pragma unroll
                    for (int nt = 0; nt < 4; nt++)
                        mma16816(acc[mt][nt], a[mt], b[nt]);
            }
        }
        __syncthreads();

        const int row0 = ty * 128, col0 = tx * 128;
        const int erow = wm * 64 + (lane >> 2);
        const int ecol = wn * 32 + (lane & 3) * 2;

        if (p.mode == 0) {
            long long coff = zo * p.sCo + zi * p.sCi;
            #pragma unroll
            for (int mt = 0; mt < 4; mt++)
                #pragma unroll
                for (int half = 0; half < 2; half++) {
                    int gr = row0 + erow + mt * 16 + half * 8;
                    long long rb = (long long)gr * p.ldc + col0 + ecol + coff;
                    #pragma unroll
                    for (int nt = 0; nt < 4; nt++) {
                        float2 v;
                        v.x = acc[mt][nt][half * 2 + 0] * p.alpha;
                        v.y = acc[mt][nt][half * 2 + 1] * p.alpha;
                        if (p.Add) {
                            float2 ad = *(const float2*)(p.Add + rb + nt * 8);
                            v.x += ad.x; v.y += ad.y;
                        }
                        *(float2*)(p.C + rb + nt * 8) = v;
                    }
                }
        } else if (p.mode == 3) {
            int b = z >> 4, h = z & 15;
            #pragma unroll
            for (int mt = 0; mt < 4; mt++)
                #pragma unroll
                for (int half = 0; half < 2; half++) {
                    int gr = row0 + erow + mt * 16 + half * 8;
                    long long base = ((long long)(b * CS + gr)) * (3LL * CD)
                                     + h * CAHD + col0 + ecol;
                    #pragma unroll
                    for (int nt = 0; nt < 4; nt++) {
                        float v0 = acc[mt][nt][half * 2 + 0];
                        float v1 = acc[mt][nt][half * 2 + 1];
                        __nv_bfloat16 h0, l0, h1, l1;
                        split2(v0, h0, l0); split2(v1, h1, l1);
                        __nv_bfloat162 hh = __nv_bfloat162(h0, h1);
                        __nv_bfloat162 ll = __nv_bfloat162(l0, l1);
                        __nv_bfloat16* d0 = (__nv_bfloat16*)(p.S3 + base + nt * 8);
                        *(__nv_bfloat162*)(d0)          = hh;
                        *(__nv_bfloat162*)(d0 + CD)     = hh;
                        *(__nv_bfloat162*)(d0 + 2 * CD) = ll;
                    }
                }
        } else {
            #pragma unroll
            for (int mt = 0; mt < 4; mt++)
                #pragma unroll
                for (int half = 0; half < 2; half++) {
                    int gr = row0 + erow + mt * 16 + half * 8;
                    long long rowb = (long long)gr * (3LL * CD);
                    #pragma unroll
                    for (int nt = 0; nt < 4; nt++) {
                        int n = col0 + ecol + nt * 8;
                        int hh_ = n >> 7, d = n & 127;
                        long long base = rowb + hh_ * 384 + d;
                        float v0 = acc[mt][nt][half * 2 + 0];
                        float v1 = acc[mt][nt][half * 2 + 1];
                        __nv_bfloat16 h0, l0, h1, l1;
                        split2(v0, h0, l0); split2(v1, h1, l1);
                        __nv_bfloat162 hv = __nv_bfloat162(h0, h1);
                        __nv_bfloat162 lv = __nv_bfloat162(l0, l1);
                        __nv_bfloat16* dp = p.S3 + base;
                        *(__nv_bfloat162*)(dp)       = hv;
                        *(__nv_bfloat162*)(dp + 128) = (p.mode == 1) ? hv : lv;
                        *(__nv_bfloat162*)(dp + 256) = (p.mode == 1) ? lv : hv;
                    }
                }
        }
    }
}

// =================== elementwise / prep kernels ===================

__global__ void rmsnorm_split_kernel(const float* __restrict__ in, const float* __restrict__ w,
                                     float* __restrict__ outf, __nv_bfloat16* __restrict__ out3,
                                     int Ktot, int colofs) {
    long long row = blockIdx.x;
    const float* ip = in + row * CD;
    float vals[8], ss = 0.f;
    #pragma unroll
    for (int ii = 0; ii < 8; ii++) {
        float u = ip[threadIdx.x + ii * 256];
        vals[ii] = u; ss = fmaf(u, u, ss);
    }
    ss = blockSum(ss);
    float rs = rsqrtf(ss * (1.f / CD) + 1e-6f);
    long long b3 = row * 3LL * Ktot + colofs;
    #pragma unroll
    for (int ii = 0; ii < 8; ii++) {
        int i = threadIdx.x + ii * 256;
        float u = vals[ii] * rs * w[i];
        if (outf) outf[row * CD + i] = u;
        __nv_bfloat16 hi, lo; split2(u, hi, lo);
        out3[b3 + i] = hi;
        out3[b3 + Ktot + i] = hi;
        out3[b3 + 2 * Ktot + i] = lo;
    }
}

__global__ void colmean_kernel(const float* __restrict__ xn, float* __restrict__ xm) {
    int idx = blockIdx.x * blockDim.x + threadIdx.x;
    int b = idx / CD, d = idx % CD;
    float s = 0.f;
    for (int t = 0; t < CS; t++) s += xn[((long long)b * CS + t) * CD + d];
    xm[idx] = s * (1.f / CS);
}

__global__ void mlp2_kernel(const float* __restrict__ xm, const float* __restrict__ wc1,
                            const float* __restrict__ bc1, float* __restrict__ h) {
    int b = blockIdx.y, c = blockIdx.x * 256 + threadIdx.x;
    float s = 0.f;
    for (int k = 0; k < CD; k++) s = fmaf(xm[b * CD + k], wc1[(long long)k * CDQ + c], s);
    s += bc1[c];
    h[b * CDQ + c] = s / (1.f + expf(-s));
}

__global__ void coeff2_kernel(const float* __restrict__ h, const float* __restrict__ wc2,
                              const float* __restrict__ bc2, float* __restrict__ coef) {
    int b = blockIdx.y, c = blockIdx.x * 256 + threadIdx.x;
    float s = 0.f;
    for (int k = 0; k < CDQ; k++) s = fmaf(h[b * CDQ + k], wc2[(long long)k * CNC + c], s);
    s += bc2[c];
    int kdeg = (c / CHD) % CDEG;
    coef[(long long)b * CNC + c] = s * (0.1f / (float)(kdeg + 1));
}

// coeff3: padded A-operand for CW1 GEMM. [h][row=b*4+kd (pad to 128)][3*256],
// value = coef * w_nc (A-side split hi,hi,lo)
__global__ void coeff3_kernel(const float* __restrict__ coef, const float* __restrict__ wnc,
                              __nv_bfloat16* __restrict__ cf3) {
    int h = blockIdx.x, r = blockIdx.y, i = threadIdx.x;   // i < 256
    float val = 0.f;
    if (r < 16) {
        int b = r >> 2, kd = r & 3;
        val = coef[(long long)b * CNC + (h * 4 + kd) * CHD + i] * wnc[h * CHD + i];
    }
    __nv_bfloat16 hi, lo; split2(val, hi, lo);
    long long base = ((long long)h * 128 + r) * 768;
    cf3[base + i] = hi;
    cf3[base + 256 + i] = hi;
    cf3[base + 512 + i] = lo;
}

// cheby v3: writes kv3 split, rs*T split (tsc3). No fp32 cheby.
__global__ void cheby3_kernel(const float* __restrict__ xn, const float* __restrict__ coef,
                              __nv_bfloat16* __restrict__ kv3, __nv_bfloat16* __restrict__ tsc3) {
    long long bs = blockIdx.x;
    int b = (int)(bs / CS);
    int w = threadIdx.x >> 5, lane = threadIdx.x & 31;
    const float* u = xn + bs * CD + w * CHD;
    float s = 0.f;
    #pragma unroll
    for (int i = lane; i < CHD; i += 32) s += u[i];
    s = warpSum(s);
    float z = tanhf(s * (1.f / CHD));
    float T1 = z, T2 = 2.f * z * z - 1.f, T3 = 2.f * z * T2 - T1;
    const float* cp = coef + (((long long)b * CNH + w) * CDEG) * CHD;
    long long b3 = bs * (3LL * CD) + w * CHD;
    float ssloc = 0.f;
    #pragma unroll
    for (int i = lane; i < CHD; i += 32) {
        float o = cp[i] + T1 * cp[CHD + i] + T2 * cp[2 * CHD + i] + T3 * cp[3 * CHD + i];
        ssloc = fmaf(o, o, ssloc);
        float val = u[i] + o;
        __nv_bfloat16 hi, lo; split2(val, hi, lo);
        kv3[b3 + i] = hi;
        kv3[b3 + CD + i] = hi;
        kv3[b3 + 2 * CD + i] = lo;
    }
    float ss = blockSum(ssloc);
    float rs = rsqrtf(ss * (1.f / CD) + 1e-6f);
    if (lane < 4) {
        float tv = (lane == 0) ? 1.f : (lane == 1) ? T1 : (lane == 2) ? T2 : T3;
        tv *= rs;
        __nv_bfloat16 hi, lo; split2(tv, hi, lo);
        long long base = bs * 96 + w * 4 + lane;
        tsc3[base]      = hi;
        tsc3[base + 32] = hi;
        tsc3[base + 64] = lo;
    }
}

// transpose + B-side split (hi,lo,hi): W[K,N] fp32 (row stride N) -> Y[N,3K] bf16
__global__ void transpose_split_kernel(const float* __restrict__ W, __nv_bfloat16* __restrict__ Y,
                                       int K, int N) {
    __shared__ float t[32][33];
    int k0 = blockIdx.y * 32, n0 = blockIdx.x * 32;
    int tx = threadIdx.x, ty = threadIdx.y;
    #pragma unroll
    for (int i = 0; i < 4; i++) {
        int k = k0 + ty + i * 8;
        t[ty + i * 8][tx] = W[(long long)k * N + n0 + tx];
    }
    __syncthreads();
    #pragma unroll
    for (int i = 0; i < 4; i++) {
        int n = n0 + ty + i * 8;
        int k = k0 + tx;
        float a = t[tx][ty + i * 8];
        __nv_bfloat16 hi, lo; split2(a, hi, lo);
        long long base = (long long)n * 3 * K;
        Y[base + k] = hi;
        Y[base + K + k] = lo;
        Y[base + 2 * K + k] = hi;
    }
}

// wfgv TOP half -> per-head transposed split: Y[h][n][3*256]
__global__ void wt1_split_kernel(const float* __restrict__ W, __nv_bfloat16* __restrict__ Y) {
    __shared__ float t[32][33];
    int k0 = blockIdx.y * 32, n0 = blockIdx.x * 32;   // k over [0,2048), n over [0,4096)
    int tx = threadIdx.x, ty = threadIdx.y;
    #pragma unroll
    for (int i = 0; i < 4; i++) {
        int k = k0 + ty + i * 8;
        t[ty + i * 8][tx] = W[(long long)k * (2 * CD) + n0 + tx];
    }
    __syncthreads();
    #pragma unroll
    for (int i = 0; i < 4; i++) {
        int n = n0 + ty + i * 8;
        int k = k0 + tx;
        int h = k >> 8, d = k & 255;
        float a = t[tx][ty + i * 8];
        __nv_bfloat16 hi, lo; split2(a, hi, lo);
        long long base = ((long long)h * (2 * CD) + n) * 768;
        Y[base + d] = hi;
        Y[base + 256 + d] = lo;
        Y[base + 512 + d] = hi;
    }
}

// CW1 [h][128][4096] fp32 -> CW1T3 [b][n][96] B-side split (hi,lo,hi)
__global__ void cw1t_kernel(const float* __restrict__ CW1, __nv_bfloat16* __restrict__ Y) {
    int n = blockIdx.x * 256 + threadIdx.x;
    int b = blockIdx.y;
    long long obase = ((long long)b * (2 * CD) + n) * 96;
    #pragma unroll
    for (int j = 0; j < 32; j++) {
        int h = j >> 2, kd = j & 3;
        float v = CW1[(((long long)h * 128) + b * 4 + kd) * (2 * CD) + n];
        __nv_bfloat16 hi, lo; split2(v, hi, lo);
        Y[obase + j] = hi;
        Y[obase + 32 + j] = lo;
        Y[obase + 64 + j] = hi;
    }
}

// per-head V transpose + B-side split
__global__ void vtrans_split_kernel(const float* __restrict__ v, __nv_bfloat16* __restrict__ vt3) {
    __shared__ float t[32][33];
    int bh = blockIdx.z, b = bh >> 4, h = bh & 15;
    int k0 = blockIdx.x * 32, n0 = blockIdx.y * 32;
    int tx = threadIdx.x, ty = threadIdx.y;
    #pragma unroll
    for (int i = 0; i < 4; i++) {
        int k = k0 + ty + i * 8;
        t[ty + i * 8][tx] = v[((long long)(b * CS + k)) * CD + h * CAHD + n0 + tx];
    }
    __syncthreads();
    #pragma unroll
    for (int i = 0; i < 4; i++) {
        int n = n0 + ty + i * 8;
        float a = t[tx][ty + i * 8];
        __nv_bfloat16 hi, lo; split2(a, hi, lo);
        long long base = ((long long)bh * CAHD + n) * (3 * CS);
        vt3[base + k0 + tx] = hi;
        vt3[base + CS + k0 + tx] = lo;
        vt3[base + 2 * CS + k0 + tx] = hi;
    }
}

__global__ void fuse_split_kernel(const float* __restrict__ gv, const float* __restrict__ wnp,
                                  __nv_bfloat16* __restrict__ out3) {
    long long row = blockIdx.x;
    const float* gp = gv + row * (2 * CD);
    float t[8], ss = 0.f;
    #pragma unroll
    for (int ii = 0; ii < 8; ii++) {
        int i = threadIdx.x + ii * 256;
        float g = gp[i], v = gp[CD + i];
        float u = g / (1.f + expf(-g)) * v;
        t[ii] = u; ss = fmaf(u, u, ss);
    }
    ss = blockSum(ss);
    float rs = rsqrtf(ss * (1.f / CD) + 1e-6f);
    long long b3 = row * (3LL * CD);
    #pragma unroll
    for (int ii = 0; ii < 8; ii++) {
        int i = threadIdx.x + ii * 256;
        float u = t[ii] * rs * wnp[i];
        __nv_bfloat16 hi, lo; split2(u, hi, lo);
        out3[b3 + i] = hi;
        out3[b3 + CD + i] = hi;
        out3[b3 + 2 * CD + i] = lo;
    }
}

__global__ void softmax_split_kernel(const float* __restrict__ sc, __nv_bfloat16* __restrict__ p3) {
    long long row = blockIdx.x;
    int i = (int)(row % CS);
    const float* sp = sc + row * CS;
    float e[2];
    float m = -1e30f;
    #pragma unroll
    for (int t = 0; t < 2; t++) { int j = threadIdx.x + t * 256; if (j <= i) m = fmaxf(m, sp[j]); }
    m = blockMax(m);
    float s = 0.f;
    #pragma unroll
    for (int t = 0; t < 2; t++) {
        int j = threadIdx.x + t * 256;
        float ev = (j <= i) ? expf(sp[j] - m) : 0.f;
        e[t] = ev; s += ev;
    }
    s = blockSum(s);
    float inv = 1.f / s;
    long long b3 = row * (3LL * CS);
    #pragma unroll
    for (int t = 0; t < 2; t++) {
        int j = threadIdx.x + t * 256;
        float u = e[t] * inv;
        __nv_bfloat16 hi, lo; split2(u, hi, lo);
        p3[b3 + j] = hi;
        p3[b3 + CS + j] = hi;
        p3[b3 + 2 * CS + j] = lo;
    }
}

// ---------------- host ----------------
static int g_grid = 296;

static void mm(const __nv_bfloat16* A, const __nv_bfloat16* B, float* C, const float* Add,
               __nv_bfloat16* S3, int M, int N, int K3, int lda, int ldb, int ldc, float alpha,
               int bz, int bdiv, long long sAo, long long sAi, long long sBo, long long sBi,
               long long sCo, long long sCi, int mode, int causal) {
    MMParams p;
    p.A = A; p.B = B; p.C = C; p.Add = Add; p.S3 = S3;
    p.lda = lda; p.ldb = ldb; p.ldc = ldc; p.K3 = K3; p.alpha = alpha;
    p.bdiv = bdiv; p.sAo = sAo; p.sAi = sAi; p.sBo = sBo; p.sBi = sBi;
    p.sCo = sCo; p.sCi = sCi;
    p.tilesM = M / 128; p.tilesN = N / 128;
    p.total = bz * p.tilesM * p.tilesN;
    p.mode = mode; p.causal = causal;
    int grid = g_grid < p.total ? g_grid : p.total;
    mm_bf16_kernel<<<grid, 256, MM_SMEM>>>(p);
}

extern "C" void kernel_launch(void* const* d_in, const int* in_sizes, int n_in,
                              void* d_out, int out_size) {
    const float* x     = (const float*)d_in[0];
    const float* w_in  = (const float*)d_in[1];
    const float* wc1   = (const float*)d_in[6];
    const float* bc1   = (const float*)d_in[7];
    const float* wc2   = (const float*)d_in[8];
    const float* bc2   = (const float*)d_in[9];
    const float* wq    = (const float*)d_in[10];
    const float* wk    = (const float*)d_in[11];
    const float* wv    = (const float*)d_in[12];
    const float* wo    = (const float*)d_in[13];
    const float* w_nc  = (const float*)d_in[14];
    const float* w_ns  = (const float*)d_in[15];
    const float* w_fgv = (const float*)d_in[16];
    const float* w_np  = (const float*)d_in[17];
    const float* w_out = (const float*)d_in[18];
    float* out = (float*)d_out;

    int smc = 148;
    cudaDeviceGetAttribute(&smc, cudaDevAttrMultiProcessorCount, 0);
    g_grid = 2 * smc;

    cudaFuncSetAttribute(mm_bf16_kernel, cudaFuncAttributeMaxDynamicSharedMemorySize, MM_SMEM);

    float *xn, *xm, *hs, *coef, *v, *sc, *slr, *gvb, *cw1;
    cudaGetSymbolAddress((void**)&xn,   g_xn);
    cudaGetSymbolAddress((void**)&xm,   g_xmean);
    cudaGetSymbolAddress((void**)&hs,   g_hs);
    cudaGetSymbolAddress((void**)&coef, g_coef);
    cudaGetSymbolAddress((void**)&v,    g_v);
    cudaGetSymbolAddress((void**)&sc,   g_sc);
    cudaGetSymbolAddress((void**)&slr,  g_slr);
    cudaGetSymbolAddress((void**)&gvb,  g_gv);
    cudaGetSymbolAddress((void**)&cw1,  g_cw1);

    __nv_bfloat16 *xn3, *kv3, *attn3, *fus3, *h23, *q3, *k3, *p3, *vt3;
    __nv_bfloat16 *wq3, *wk3, *wv3, *wo3, *wout3, *wfgvb3, *wt13, *cf3, *cw1t3, *tsc3;
    cudaGetSymbolAddress((void**)&xn3,    g3_xn);
    cudaGetSymbolAddress((void**)&kv3,    g3_kv);
    cudaGetSymbolAddress((void**)&attn3,  g3_attn);
    cudaGetSymbolAddress((void**)&fus3,   g3_fus);
    cudaGetSymbolAddress((void**)&h23,    g3_h2);
    cudaGetSymbolAddress((void**)&q3,     g3_q);
    cudaGetSymbolAddress((void**)&k3,     g3_k);
    cudaGetSymbolAddress((void**)&p3,     g3_p);
    cudaGetSymbolAddress((void**)&vt3,    g3_vt);
    cudaGetSymbolAddress((void**)&wq3,    g3_wq);
    cudaGetSymbolAddress((void**)&wk3,    g3_wk);
    cudaGetSymbolAddress((void**)&wv3,    g3_wv);
    cudaGetSymbolAddress((void**)&wo3,    g3_wo);
    cudaGetSymbolAddress((void**)&wout3,  g3_wout);
    cudaGetSymbolAddress((void**)&wfgvb3, g3_wfgvb);
    cudaGetSymbolAddress((void**)&wt13,   g3_wt1);
    cudaGetSymbolAddress((void**)&cf3,    g3_cf);
    cudaGetSymbolAddress((void**)&cw1t3,  g3_cw1t);
    cudaGetSymbolAddress((void**)&tsc3,   g3_tsc);

    // weight transposes + B-side splits
    dim3 tgrid(CD / 32, CD / 32), tblk(32, 8);
    transpose_split_kernel<<<tgrid, tblk>>>(wq,    wq3,   CD, CD);
    transpose_split_kernel<<<tgrid, tblk>>>(wk,    wk3,   CD, CD);
    transpose_split_kernel<<<tgrid, tblk>>>(wv,    wv3,   CD, CD);
    transpose_split_kernel<<<tgrid, tblk>>>(wo,    wo3,   CD, CD);
    transpose_split_kernel<<<tgrid, tblk>>>(w_out, wout3, CD, CD);
    // fgv bottom half (rows 2048..4095): Y [4096][3*2048]
    transpose_split_kernel<<<dim3((2 * CD) / 32, CD / 32), tblk>>>(
        w_fgv + (long long)CD * (2 * CD), wfgvb3, CD, 2 * CD);
    // fgv top half per-head: Y [8][4096][768]
    wt1_split_kernel<<<dim3((2 * CD) / 32, CD / 32), tblk>>>(w_fgv, wt13);

    // activations prep
    rmsnorm_split_kernel<<<MT, 256>>>(x, w_in, xn, xn3, CD, 0);
    colmean_kernel<<<(CB * CD) / 256, 256>>>(xn, xm);
    mlp2_kernel<<<dim3(CDQ / 256, CB), 256>>>(xm, wc1, bc1, hs);
    coeff2_kernel<<<dim3(CNC / 256, CB), 256>>>(hs, wc2, bc2, coef);
    coeff3_kernel<<<dim3(8, 128), 256>>>(coef, w_nc, cf3);
    cheby3_kernel<<<MT, 256>>>(xn, coef, kv3, tsc3);

    // CW1 = coeff3 @ WT1 (batched over 8 heads)
    mm(cf3, wt13, cw1, 0, 0, 128, 2 * CD, 768, 768, 768, 2 * CD, 1.f,
       8, 1, (long long)128 * 768, 0, (long long)(2 * CD) * 768, 0,
       (long long)128 * (2 * CD), 0, 0, 0);
    cw1t_kernel<<<dim3((2 * CD) / 256, CB), 256>>>(cw1, cw1t3);

    // q/k projections -> head-split epilogues; v -> fp32
    mm(xn3, wq3, 0, 0, q3, MT, CD, 3 * CD, 3 * CD, 3 * CD, CD, 1.f,
       1, 1, 0, 0, 0, 0, 0, 0, 1, 0);
    mm(kv3, wk3, 0, 0, k3, MT, CD, 3 * CD, 3 * CD, 3 * CD, CD, 1.f,
       1, 1, 0, 0, 0, 0, 0, 0, 2, 0);
    mm(kv3, wv3, v, 0, 0, MT, CD, 3 * CD, 3 * CD, 3 * CD, CD, 1.f,
       1, 1, 0, 0, 0, 0, 0, 0, 0, 0);

    vtrans_split_kernel<<<dim3(CS / 32, CAHD / 32, CB * CAH), tblk>>>(v, vt3);

    // scores = q @ k^T / sqrt(hd) with causal tile skip
    mm(q3, k3, sc, 0, 0, CS, CS, 384, 3 * CD, 3 * CD, CS, 0.08838834764831845f,
       CB * CAH, CAH,
       (long long)CS * 3 * CD, 384,
       (long long)CS * 3 * CD, 384,
       (long long)CAH * CS * CS, (long long)CS * CS, 0, 1);

    softmax_split_kernel<<<CB * CAH * CS, 256>>>(sc, p3);

    // attn = P @ V -> attn3 split epilogue
    mm(p3, vt3, 0, 0, attn3, CS, CAHD, 3 * CS, 3 * CS, 3 * CS, CD, 1.f,
       CB * CAH, CAH,
       (long long)CAH * CS * 3 * CS, (long long)CS * 3 * CS,
       (long long)CAH * CAHD * 3 * CS, (long long)CAHD * 3 * CS,
       0, 0, 3, 0);

    // slr = attn @ wo
    mm(attn3, wo3, slr, 0, 0, MT, CD, 3 * CD, 3 * CD, 3 * CD, CD, 1.f,
       1, 1, 0, 0, 0, 0, 0, 0, 0, 0);

    // h2 = split(rmsnorm(slr, w_ns))
    rmsnorm_split_kernel<<<MT, 256>>>(slr, w_ns, 0, h23, CD, 0);

    // gv = (rs*T) @ CW1^T  (low-rank h1 path, batched over b)
    mm(tsc3, cw1t3, gvb, 0, 0, CS, 2 * CD, 96, 96, 96, 2 * CD, 1.f,
       CB, 1, (long long)CS * 96, 0, (long long)(2 * CD) * 96, 0,
       (long long)CS * (2 * CD), 0, 0, 0);
    // gv += h2 @ wfgv_bottom
    mm(h23, wfgvb3, gvb, gvb, 0, MT, 2 * CD, 3 * CD, 3 * CD, 3 * CD, 2 * CD, 1.f,
       1, 1, 0, 0, 0, 0, 0, 0, 0, 0);

    // fused, then out = x + fused @ w_out
    fuse_split_kernel<<<MT, 256>>>(gvb, w_np, fus3);
    mm(fus3, wout3, out, x, 0, MT, CD, 3 * CD, 3 * CD, 3 * CD, CD, 1.f,
       1, 1, 0, 0, 0, 0, 0, 0, 0, 0);
}